// round 1
// baseline (speedup 1.0000x reference)
#include <cuda_runtime.h>
#include <cuda_bf16.h>
#include <math.h>

// Problem constants
#define BB 4
#define SS 1024
#define HH 2048
#define NH 32
#define NKV 8
#define HD 64
#define NROWS (BB*SS)          // 4096
#define QW (NH*HD)             // 2048
#define KW (NKV*HD)            // 512

// Scratch (device globals; no allocation allowed)
__device__ float g_Q[NROWS * QW];
__device__ float g_K[NROWS * KW];
__device__ float g_V[NROWS * KW];
__device__ float g_AO[NROWS * QW];

// ---------------------------------------------------------------------------
// SGEMM: C[M,N] = A[M,K] @ B[K,N], row-major, 128x128x8 tile, 8x8 per thread
// ---------------------------------------------------------------------------
#define BM 128
#define BN 128
#define BK 8

__global__ __launch_bounds__(256) void sgemm_kernel(
    const float* __restrict__ A, const float* __restrict__ B,
    float* __restrict__ C, int M, int N, int K)
{
    __shared__ float As[BK][BM];
    __shared__ float Bs[BK][BN];

    const int bx = blockIdx.x;   // N tile
    const int by = blockIdx.y;   // M tile
    const int tid = threadIdx.x; // 256
    const int tx = tid & 15;
    const int ty = tid >> 4;

    const float* Ap = A + (size_t)by * BM * K;
    const float* Bp = B + (size_t)bx * BN;

    const int arow = tid >> 1;           // 128 rows, 2 threads/row
    const int acol = (tid & 1) * 4;      // 4 floats each
    const int brow = tid >> 6;           // 8? no: need 8 rows coverage
    // B tile: 8 rows x 128 cols = 1024 floats; 256 threads load 4 each
    const int b_r = tid >> 5;            // 0..7
    const int b_c = (tid & 31) * 4;      // 0..124

    float acc[8][8];
#pragma unroll
    for (int i = 0; i < 8; i++)
#pragma unroll
        for (int j = 0; j < 8; j++) acc[i][j] = 0.f;

    for (int k0 = 0; k0 < K; k0 += BK) {
        float4 av = *(const float4*)(Ap + (size_t)arow * K + k0 + acol);
        As[acol + 0][arow] = av.x;
        As[acol + 1][arow] = av.y;
        As[acol + 2][arow] = av.z;
        As[acol + 3][arow] = av.w;
        float4 bv = *(const float4*)(Bp + (size_t)(k0 + b_r) * N + b_c);
        *(float4*)&Bs[b_r][b_c] = bv;
        __syncthreads();

#pragma unroll
        for (int kk = 0; kk < BK; kk++) {
            float af[8], bf[8];
#pragma unroll
            for (int i = 0; i < 8; i++) af[i] = As[kk][ty * 8 + i];
#pragma unroll
            for (int j = 0; j < 8; j++) bf[j] = Bs[kk][tx * 8 + j];
#pragma unroll
            for (int i = 0; i < 8; i++)
#pragma unroll
                for (int j = 0; j < 8; j++) acc[i][j] += af[i] * bf[j];
        }
        __syncthreads();
    }

#pragma unroll
    for (int i = 0; i < 8; i++) {
        int row = by * BM + ty * 8 + i;
        float* cp = C + (size_t)row * N + bx * BN + tx * 8;
#pragma unroll
        for (int j = 0; j < 8; j += 4) {
            float4 v = make_float4(acc[i][j], acc[i][j+1], acc[i][j+2], acc[i][j+3]);
            *(float4*)(cp + j) = v;
        }
    }
    (void)brow;
}

// ---------------------------------------------------------------------------
// RoPE (in-place over [4096, nheads*64]); each thread handles one (row,h,pair)
// ---------------------------------------------------------------------------
__global__ void rope_kernel(float* __restrict__ T,
                            const float* __restrict__ cs,
                            const float* __restrict__ sn,
                            int nheads)
{
    int idx = blockIdx.x * blockDim.x + threadIdx.x;
    int total = NROWS * nheads * 32;
    if (idx >= total) return;
    int p   = idx & 31;
    int hh  = (idx >> 5) % nheads;
    int row = idx / (32 * nheads);

    float c1 = cs[row * HD + p];
    float c2 = cs[row * HD + p + 32];
    float s1 = sn[row * HD + p];
    float s2 = sn[row * HD + p + 32];

    float* base = T + (size_t)row * (nheads * HD) + hh * HD;
    float x1 = base[p];
    float x2 = base[p + 32];
    base[p]      = x1 * c1 - x2 * s1;   // d < 32: rot = -x[d+32]
    base[p + 32] = x2 * c2 + x1 * s2;   // d >=32: rot =  x[d-32]
}

// ---------------------------------------------------------------------------
// Attention: one block = one (b,h) + 16 query rows.
// smem: sQ[16*64], sK[64*68] (padded), sS[16*1024]
// ---------------------------------------------------------------------------
#define QT 16
#define KCH 64
#define KPAD 68
#define ATTN_SMEM ((QT*HD + KCH*KPAD + QT*SS) * 4)

__global__ __launch_bounds__(256) void attn_kernel(float* __restrict__ aw,
                                                   float* __restrict__ AO)
{
    extern __shared__ float smem[];
    float* sQ = smem;                       // 1024
    float* sK = smem + QT * HD;             // 64*68
    float* sS = sK + KCH * KPAD;            // 16*1024

    const int qt = blockIdx.x & 63;         // S/QT = 64 tiles
    const int bh = blockIdx.x >> 6;
    const int b  = bh / NH;
    const int h  = bh % NH;
    const int kvh = h / (NH / NKV);
    const int tid = threadIdx.x;
    const int q0 = qt * QT;
    const float scaling = 0.125f;           // 64^-0.5

    // load Q tile
    for (int i = tid; i < QT * HD; i += 256) {
        int r = i >> 6, d = i & 63;
        sQ[i] = g_Q[(size_t)(b * SS + q0 + r) * QW + h * HD + d];
    }

    const int c  = tid & 63;
    const int r0 = tid >> 6;   // 0..3

    for (int kt = 0; kt < SS / KCH; kt++) {
        __syncthreads();
        for (int i = tid; i < KCH * HD; i += 256) {
            int kr = i >> 6, d = i & 63;
            sK[kr * KPAD + d] = g_K[(size_t)(b * SS + kt * KCH + kr) * KW + kvh * HD + d];
        }
        __syncthreads();
#pragma unroll
        for (int rr = 0; rr < 4; rr++) {
            int r = r0 + rr * 4;
            const float4* q4 = (const float4*)(sQ + r * HD);
            const float4* k4 = (const float4*)(sK + c * KPAD);
            float sum = 0.f;
#pragma unroll
            for (int d4 = 0; d4 < HD / 4; d4++) {
                float4 a = q4[d4], kb = k4[d4];
                sum += a.x * kb.x + a.y * kb.y + a.z * kb.z + a.w * kb.w;
            }
            int kcol = kt * KCH + c;
            float v = sum * scaling + ((kcol > q0 + r) ? -1e9f : 0.f);
            sS[r * SS + kcol] = v;
        }
    }
    __syncthreads();

    // softmax: 8 warps, 2 rows each; write aw
    {
        int warp = tid >> 5, lane = tid & 31;
        for (int rw = 0; rw < 2; rw++) {
            int r = warp * 2 + rw;
            float* row = sS + r * SS;
            float m = -INFINITY;
            for (int cc = lane; cc < SS; cc += 32) m = fmaxf(m, row[cc]);
#pragma unroll
            for (int o = 16; o; o >>= 1) m = fmaxf(m, __shfl_xor_sync(0xffffffffu, m, o));
            float ssum = 0.f;
            for (int cc = lane; cc < SS; cc += 32) {
                float p = expf(row[cc] - m);
                row[cc] = p;
                ssum += p;
            }
#pragma unroll
            for (int o = 16; o; o >>= 1) ssum += __shfl_xor_sync(0xffffffffu, ssum, o);
            float inv = 1.f / ssum;
            float* awrow = aw + ((size_t)(bh * SS + q0 + r)) * SS;
            for (int cc = lane; cc < SS; cc += 32) {
                float p = row[cc] * inv;
                row[cc] = p;
                awrow[cc] = p;
            }
        }
    }
    __syncthreads();

    // PV: each thread owns (r, d..d+3)
    {
        const int d  = (tid & 15) * 4;
        const int r  = tid >> 4;
        float4 acc = make_float4(0.f, 0.f, 0.f, 0.f);
        for (int vt = 0; vt < SS / KCH; vt++) {
            __syncthreads();
            for (int i = tid; i < KCH * HD; i += 256) {
                int vr = i >> 6, dd = i & 63;
                sK[vr * KPAD + dd] = g_V[(size_t)(b * SS + vt * KCH + vr) * KW + kvh * HD + dd];
            }
            __syncthreads();
            const float* prow = sS + r * SS + vt * KCH;
#pragma unroll 8
            for (int cc = 0; cc < KCH; cc++) {
                float p = prow[cc];
                float4 v4 = *(const float4*)(sK + cc * KPAD + d);
                acc.x += p * v4.x;
                acc.y += p * v4.y;
                acc.z += p * v4.z;
                acc.w += p * v4.w;
            }
        }
        float* o = g_AO + (size_t)(b * SS + q0 + r) * QW + h * HD + d;
        *(float4*)o = acc;
    }
}

// ---------------------------------------------------------------------------
// Launch
// ---------------------------------------------------------------------------
extern "C" void kernel_launch(void* const* d_in, const int* in_sizes, int n_in,
                              void* d_out, int out_size)
{
    const float* x    = (const float*)d_in[0];
    const float* cs   = (const float*)d_in[1];
    const float* sn   = (const float*)d_in[2];
    // d_in[3] = attention_mask (pure causal -1e9; reproduced analytically)
    const float* Wq   = (const float*)d_in[4];
    const float* Wk   = (const float*)d_in[5];
    const float* Wv   = (const float*)d_in[6];
    const float* Wo   = (const float*)d_in[7];

    float* out = (float*)d_out;                       // (B,S,H)
    float* aw  = out + (size_t)NROWS * HH;            // (B,NH,S,S)

    float *Qp, *Kp, *Vp, *AOp;
    cudaGetSymbolAddress((void**)&Qp,  g_Q);
    cudaGetSymbolAddress((void**)&Kp,  g_K);
    cudaGetSymbolAddress((void**)&Vp,  g_V);
    cudaGetSymbolAddress((void**)&AOp, g_AO);

    cudaFuncSetAttribute(attn_kernel, cudaFuncAttributeMaxDynamicSharedMemorySize, ATTN_SMEM);

    // Projections
    {
        dim3 g(QW / BN, NROWS / BM);
        sgemm_kernel<<<g, 256>>>(x, Wq, Qp, NROWS, QW, HH);
    }
    {
        dim3 g(KW / BN, NROWS / BM);
        sgemm_kernel<<<g, 256>>>(x, Wk, Kp, NROWS, KW, HH);
        sgemm_kernel<<<g, 256>>>(x, Wv, Vp, NROWS, KW, HH);
    }

    // RoPE
    {
        int totq = NROWS * NH * 32;
        rope_kernel<<<(totq + 255) / 256, 256>>>(Qp, cs, sn, NH);
        int totk = NROWS * NKV * 32;
        rope_kernel<<<(totk + 255) / 256, 256>>>(Kp, cs, sn, NKV);
    }

    // Attention (+ aw output)
    {
        int grid = BB * NH * (SS / QT);   // 8192
        attn_kernel<<<grid, 256, ATTN_SMEM>>>(aw, AOp);
    }

    // Output projection -> out
    {
        dim3 g(HH / BN, NROWS / BM);
        sgemm_kernel<<<g, 256>>>(AOp, Wo, out, NROWS, HH, QW);
    }

    (void)in_sizes; (void)n_in; (void)out_size;
}

// round 7
// speedup vs baseline: 1.2569x; 1.2569x over previous
#include <cuda_runtime.h>
#include <cuda_bf16.h>
#include <cstdint>
#include <math.h>

// Problem constants
#define BB 4
#define SS 1024
#define HH 2048
#define NH 32
#define NKV 8
#define HD 64
#define NROWS (BB*SS)          // 4096
#define QW (NH*HD)             // 2048
#define KW (NKV*HD)            // 512

// Scratch (device globals; no allocation allowed)
__device__ float g_Q[NROWS * QW];
__device__ float g_K[NROWS * KW];
__device__ float g_V[NROWS * KW];
__device__ float g_AO[NROWS * QW];

// ---------------------------------------------------------------------------
// 3xTF32 tensor-core GEMM: C[M,N] = A[M,K] @ B[K,N], row-major.
// 128x128x32 tile, 256 threads (8 warps, warp tile 32x64), cp.async double buf.
// Each operand split hi/lo; 3 mmas per fragment pair -> ~fp32 accuracy.
// ---------------------------------------------------------------------------
#define BM 128
#define BN 128
#define BK 32
#define AST 36          // As row stride (floats): bank-conflict-free frag loads
#define BST 136         // Bs row stride (floats)
#define ASIZE (BM*AST)  // 4608 floats
#define BSIZE (BK*BST)  // 4352 floats
#define GEMM_SMEM ((2*ASIZE + 2*BSIZE)*4)   // 71680 B

__device__ __forceinline__ void cp16(unsigned int dst, const void* src) {
    asm volatile("cp.async.cg.shared.global [%0], [%1], 16;\n" :: "r"(dst), "l"(src));
}

__device__ __forceinline__ unsigned int tf32_of(float x) {
    unsigned int r;
    asm("cvt.rna.tf32.f32 %0, %1;\n" : "=r"(r) : "f"(x));
    return r;
}

__device__ __forceinline__ void mma_tf32u(float* c, const unsigned int* a,
                                          const unsigned int* b) {
    asm volatile(
        "mma.sync.aligned.m16n8k8.row.col.f32.tf32.tf32.f32 "
        "{%0,%1,%2,%3}, {%4,%5,%6,%7}, {%8,%9}, {%0,%1,%2,%3};\n"
        : "+f"(c[0]), "+f"(c[1]), "+f"(c[2]), "+f"(c[3])
        : "r"(a[0]), "r"(a[1]), "r"(a[2]), "r"(a[3]),
          "r"(b[0]), "r"(b[1]));
}

__global__ __launch_bounds__(256) void gemm_tf32(
    const float* __restrict__ A, const float* __restrict__ B,
    float* __restrict__ C, int M, int N, int K)
{
    extern __shared__ float smem[];
    float* Asm = smem;                 // 2 * ASIZE
    float* Bsm = smem + 2 * ASIZE;     // 2 * BSIZE

    const int tid = threadIdx.x;
    const int wid = tid >> 5, lane = tid & 31;
    const int g = lane >> 2, tg = lane & 3;
    const int warp_m = wid & 3;        // 0..3 -> 32-row slice
    const int warp_n = wid >> 2;       // 0..1 -> 64-col slice
    const int bx = blockIdx.x, by = blockIdx.y;

    // global load mapping
    const int a_row = tid >> 3;              // 0..31
    const int a_col = (tid & 7) * 4;         // 0..28
    const int b_row = tid >> 5;              // 0..7
    const int b_col = (tid & 31) * 4;        // 0..124

    const float* Ag = A + (size_t)(by * BM + a_row) * K + a_col;
    const float* Bg = B + (size_t)b_row * N + bx * BN + b_col;

    unsigned int as_base = (unsigned int)__cvta_generic_to_shared(Asm);
    unsigned int bs_base = (unsigned int)__cvta_generic_to_shared(Bsm);

    float acc[2][8][4];
#pragma unroll
    for (int i = 0; i < 2; i++)
#pragma unroll
        for (int j = 0; j < 8; j++)
#pragma unroll
            for (int q = 0; q < 4; q++) acc[i][j][q] = 0.f;

    const int KT = K / BK;

    auto load_tile = [&](int buf, int k0) {
#pragma unroll
        for (int i = 0; i < 4; i++) {
            unsigned int dst = as_base + buf * (ASIZE * 4)
                             + ((a_row + i * 32) * AST + a_col) * 4;
            cp16(dst, Ag + (size_t)(i * 32) * K + k0);
        }
#pragma unroll
        for (int i = 0; i < 4; i++) {
            unsigned int dst = bs_base + buf * (BSIZE * 4)
                             + ((b_row + i * 8) * BST + b_col) * 4;
            cp16(dst, Bg + (size_t)(k0 + i * 8) * N);
        }
        asm volatile("cp.async.commit_group;\n");
    };

    load_tile(0, 0);

    for (int kt = 0; kt < KT; kt++) {
        const int cur = kt & 1;
        if (kt + 1 < KT) {
            load_tile(cur ^ 1, (kt + 1) * BK);
            asm volatile("cp.async.wait_group 1;\n");
        } else {
            asm volatile("cp.async.wait_group 0;\n");
        }
        __syncthreads();

        const float* As = Asm + cur * ASIZE;
        const float* Bs = Bsm + cur * BSIZE;
        const int m0 = warp_m * 32;
        const int n0 = warp_n * 64;

#pragma unroll
        for (int kk = 0; kk < 4; kk++) {
            unsigned int afh[2][4], afl[2][4];
#pragma unroll
            for (int mf = 0; mf < 2; mf++) {
                const float* ap = As + (m0 + mf * 16 + g) * AST + kk * 8 + tg;
                float v0 = ap[0];
                float v1 = ap[8 * AST];
                float v2 = ap[4];
                float v3 = ap[8 * AST + 4];
                afh[mf][0] = tf32_of(v0);
                afh[mf][1] = tf32_of(v1);
                afh[mf][2] = tf32_of(v2);
                afh[mf][3] = tf32_of(v3);
                afl[mf][0] = tf32_of(v0 - __uint_as_float(afh[mf][0]));
                afl[mf][1] = tf32_of(v1 - __uint_as_float(afh[mf][1]));
                afl[mf][2] = tf32_of(v2 - __uint_as_float(afh[mf][2]));
                afl[mf][3] = tf32_of(v3 - __uint_as_float(afh[mf][3]));
            }
            unsigned int bfh[8][2], bfl[8][2];
#pragma unroll
            for (int nf = 0; nf < 8; nf++) {
                const float* bp = Bs + (kk * 8 + tg) * BST + n0 + nf * 8 + g;
                float v0 = bp[0];
                float v1 = bp[4 * BST];
                bfh[nf][0] = tf32_of(v0);
                bfh[nf][1] = tf32_of(v1);
                bfl[nf][0] = tf32_of(v0 - __uint_as_float(bfh[nf][0]));
                bfl[nf][1] = tf32_of(v1 - __uint_as_float(bfh[nf][1]));
            }
#pragma unroll
            for (int mf = 0; mf < 2; mf++)
#pragma unroll
                for (int nf = 0; nf < 8; nf++) {
                    mma_tf32u(acc[mf][nf], afl[mf], bfh[nf]);
                    mma_tf32u(acc[mf][nf], afh[mf], bfl[nf]);
                    mma_tf32u(acc[mf][nf], afh[mf], bfh[nf]);
                }
        }
        __syncthreads();
    }

    // epilogue: c0=C[g][2tg], c1=C[g][2tg+1], c2=C[g+8][2tg], c3=C[g+8][2tg+1]
#pragma unroll
    for (int mf = 0; mf < 2; mf++) {
#pragma unroll
        for (int nf = 0; nf < 8; nf++) {
            int row = by * BM + warp_m * 32 + mf * 16 + g;
            int col = bx * BN + warp_n * 64 + nf * 8 + 2 * tg;
            float* cp = C + (size_t)row * N + col;
            *(float2*)cp               = make_float2(acc[mf][nf][0], acc[mf][nf][1]);
            *(float2*)(cp + 8 * N)     = make_float2(acc[mf][nf][2], acc[mf][nf][3]);
        }
    }
}

// ---------------------------------------------------------------------------
// RoPE (in-place over [4096, nheads*64])
// ---------------------------------------------------------------------------
__global__ void rope_kernel(float* __restrict__ T,
                            const float* __restrict__ cs,
                            const float* __restrict__ sn,
                            int nheads)
{
    int idx = blockIdx.x * blockDim.x + threadIdx.x;
    int total = NROWS * nheads * 32;
    if (idx >= total) return;
    int p   = idx & 31;
    int hh  = (idx >> 5) % nheads;
    int row = idx / (32 * nheads);

    float c1 = cs[row * HD + p];
    float c2 = cs[row * HD + p + 32];
    float s1 = sn[row * HD + p];
    float s2 = sn[row * HD + p + 32];

    float* base = T + (size_t)row * (nheads * HD) + hh * HD;
    float x1 = base[p];
    float x2 = base[p + 32];
    base[p]      = x1 * c1 - x2 * s1;
    base[p + 32] = x2 * c2 + x1 * s2;
}

// ---------------------------------------------------------------------------
// Attention: one block = one (b,h) + 16 query rows
// ---------------------------------------------------------------------------
#define QT 16
#define KCH 64
#define KPAD 68
#define ATTN_SMEM ((QT*HD + KCH*KPAD + QT*SS) * 4)

__global__ __launch_bounds__(256) void attn_kernel(float* __restrict__ aw,
                                                   float* __restrict__ AO)
{
    extern __shared__ float smem[];
    float* sQ = smem;
    float* sK = smem + QT * HD;
    float* sS = sK + KCH * KPAD;

    const int qt = blockIdx.x & 63;
    const int bh = blockIdx.x >> 6;
    const int b  = bh / NH;
    const int h  = bh % NH;
    const int kvh = h / (NH / NKV);
    const int tid = threadIdx.x;
    const int q0 = qt * QT;
    const float scaling = 0.125f;

    for (int i = tid; i < QT * HD; i += 256) {
        int r = i >> 6, d = i & 63;
        sQ[i] = g_Q[(size_t)(b * SS + q0 + r) * QW + h * HD + d];
    }

    const int c  = tid & 63;
    const int r0 = tid >> 6;

    for (int kt = 0; kt < SS / KCH; kt++) {
        __syncthreads();
        for (int i = tid; i < KCH * HD; i += 256) {
            int kr = i >> 6, d = i & 63;
            sK[kr * KPAD + d] = g_K[(size_t)(b * SS + kt * KCH + kr) * KW + kvh * HD + d];
        }
        __syncthreads();
#pragma unroll
        for (int rr = 0; rr < 4; rr++) {
            int r = r0 + rr * 4;
            const float4* q4 = (const float4*)(sQ + r * HD);
            const float4* k4 = (const float4*)(sK + c * KPAD);
            float sum = 0.f;
#pragma unroll
            for (int d4 = 0; d4 < HD / 4; d4++) {
                float4 a = q4[d4], kb = k4[d4];
                sum += a.x * kb.x + a.y * kb.y + a.z * kb.z + a.w * kb.w;
            }
            int kcol = kt * KCH + c;
            float v = sum * scaling + ((kcol > q0 + r) ? -1e9f : 0.f);
            sS[r * SS + kcol] = v;
        }
    }
    __syncthreads();

    {
        int warp = tid >> 5, lane = tid & 31;
        for (int rw = 0; rw < 2; rw++) {
            int r = warp * 2 + rw;
            float* row = sS + r * SS;
            float m = -INFINITY;
            for (int cc = lane; cc < SS; cc += 32) m = fmaxf(m, row[cc]);
#pragma unroll
            for (int o = 16; o; o >>= 1) m = fmaxf(m, __shfl_xor_sync(0xffffffffu, m, o));
            float ssum = 0.f;
            for (int cc = lane; cc < SS; cc += 32) {
                float p = expf(row[cc] - m);
                row[cc] = p;
                ssum += p;
            }
#pragma unroll
            for (int o = 16; o; o >>= 1) ssum += __shfl_xor_sync(0xffffffffu, ssum, o);
            float inv = 1.f / ssum;
            float* awrow = aw + ((size_t)(bh * SS + q0 + r)) * SS;
            for (int cc = lane; cc < SS; cc += 32) {
                float p = row[cc] * inv;
                row[cc] = p;
                awrow[cc] = p;
            }
        }
    }
    __syncthreads();

    {
        const int d  = (tid & 15) * 4;
        const int r  = tid >> 4;
        float4 acc = make_float4(0.f, 0.f, 0.f, 0.f);
        for (int vt = 0; vt < SS / KCH; vt++) {
            __syncthreads();
            for (int i = tid; i < KCH * HD; i += 256) {
                int vr = i >> 6, dd = i & 63;
                sK[vr * KPAD + dd] = g_V[(size_t)(b * SS + vt * KCH + vr) * KW + kvh * HD + dd];
            }
            __syncthreads();
            const float* prow = sS + r * SS + vt * KCH;
#pragma unroll 8
            for (int cc = 0; cc < KCH; cc++) {
                float p = prow[cc];
                float4 v4 = *(const float4*)(sK + cc * KPAD + d);
                acc.x += p * v4.x;
                acc.y += p * v4.y;
                acc.z += p * v4.z;
                acc.w += p * v4.w;
            }
        }
        float* o = g_AO + (size_t)(b * SS + q0 + r) * QW + h * HD + d;
        *(float4*)o = acc;
    }
}

// ---------------------------------------------------------------------------
// Launch
// ---------------------------------------------------------------------------
extern "C" void kernel_launch(void* const* d_in, const int* in_sizes, int n_in,
                              void* d_out, int out_size)
{
    const float* x    = (const float*)d_in[0];
    const float* cs   = (const float*)d_in[1];
    const float* sn   = (const float*)d_in[2];
    // d_in[3] = attention_mask (pure causal; reproduced analytically)
    const float* Wq   = (const float*)d_in[4];
    const float* Wk   = (const float*)d_in[5];
    const float* Wv   = (const float*)d_in[6];
    const float* Wo   = (const float*)d_in[7];

    float* out = (float*)d_out;
    float* aw  = out + (size_t)NROWS * HH;

    float *Qp, *Kp, *Vp, *AOp;
    cudaGetSymbolAddress((void**)&Qp,  g_Q);
    cudaGetSymbolAddress((void**)&Kp,  g_K);
    cudaGetSymbolAddress((void**)&Vp,  g_V);
    cudaGetSymbolAddress((void**)&AOp, g_AO);

    cudaFuncSetAttribute(attn_kernel, cudaFuncAttributeMaxDynamicSharedMemorySize, ATTN_SMEM);
    cudaFuncSetAttribute(gemm_tf32, cudaFuncAttributeMaxDynamicSharedMemorySize, GEMM_SMEM);

    // Projections (3xTF32 tensor cores)
    {
        dim3 g(QW / BN, NROWS / BM);
        gemm_tf32<<<g, 256, GEMM_SMEM>>>(x, Wq, Qp, NROWS, QW, HH);
    }
    {
        dim3 g(KW / BN, NROWS / BM);
        gemm_tf32<<<g, 256, GEMM_SMEM>>>(x, Wk, Kp, NROWS, KW, HH);
        gemm_tf32<<<g, 256, GEMM_SMEM>>>(x, Wv, Vp, NROWS, KW, HH);
    }

    // RoPE
    {
        int totq = NROWS * NH * 32;
        rope_kernel<<<(totq + 255) / 256, 256>>>(Qp, cs, sn, NH);
        int totk = NROWS * NKV * 32;
        rope_kernel<<<(totk + 255) / 256, 256>>>(Kp, cs, sn, NKV);
    }

    // Attention (+ aw output)
    {
        int grid = BB * NH * (SS / QT);
        attn_kernel<<<grid, 256, ATTN_SMEM>>>(aw, AOp);
    }

    // Output projection
    {
        dim3 g(HH / BN, NROWS / BM);
        gemm_tf32<<<g, 256, GEMM_SMEM>>>(AOp, Wo, out, NROWS, HH, QW);
    }

    (void)in_sizes; (void)n_in; (void)out_size;
}

// round 8
// speedup vs baseline: 1.3714x; 1.0911x over previous
#include <cuda_runtime.h>
#include <cuda_bf16.h>
#include <cstdint>
#include <math.h>

// Problem constants
#define BB 4
#define SS 1024
#define HH 2048
#define NH 32
#define NKV 8
#define HD 64
#define NROWS (BB*SS)          // 4096
#define QW (NH*HD)             // 2048
#define KW (NKV*HD)            // 512

// Scratch (device globals; no allocation allowed)
__device__ float g_Q[NROWS * QW];
__device__ float g_K[NROWS * KW];
__device__ float g_V[NROWS * KW];
__device__ float g_AO[NROWS * QW];

// ---------------------------------------------------------------------------
// mma helpers
// ---------------------------------------------------------------------------
__device__ __forceinline__ void cp16(unsigned int dst, const void* src) {
    asm volatile("cp.async.cg.shared.global [%0], [%1], 16;\n" :: "r"(dst), "l"(src));
}

__device__ __forceinline__ unsigned int tf32_of(float x) {
    unsigned int r;
    asm("cvt.rna.tf32.f32 %0, %1;\n" : "=r"(r) : "f"(x));
    return r;
}

__device__ __forceinline__ void mma_tf32u(float* c, const unsigned int* a,
                                          const unsigned int* b) {
    asm volatile(
        "mma.sync.aligned.m16n8k8.row.col.f32.tf32.tf32.f32 "
        "{%0,%1,%2,%3}, {%4,%5,%6,%7}, {%8,%9}, {%0,%1,%2,%3};\n"
        : "+f"(c[0]), "+f"(c[1]), "+f"(c[2]), "+f"(c[3])
        : "r"(a[0]), "r"(a[1]), "r"(a[2]), "r"(a[3]),
          "r"(b[0]), "r"(b[1]));
}

// ---------------------------------------------------------------------------
// 3xTF32 tensor-core GEMM: C[M,N] = A[M,K] @ B[K,N] (unchanged from R7)
// ---------------------------------------------------------------------------
#define BM 128
#define BN 128
#define BK 32
#define AST 36
#define BST 136
#define ASIZE (BM*AST)
#define BSIZE (BK*BST)
#define GEMM_SMEM ((2*ASIZE + 2*BSIZE)*4)

__global__ __launch_bounds__(256) void gemm_tf32(
    const float* __restrict__ A, const float* __restrict__ B,
    float* __restrict__ C, int M, int N, int K)
{
    extern __shared__ float smem[];
    float* Asm = smem;
    float* Bsm = smem + 2 * ASIZE;

    const int tid = threadIdx.x;
    const int wid = tid >> 5, lane = tid & 31;
    const int g = lane >> 2, tg = lane & 3;
    const int warp_m = wid & 3;
    const int warp_n = wid >> 2;
    const int bx = blockIdx.x, by = blockIdx.y;

    const int a_row = tid >> 3;
    const int a_col = (tid & 7) * 4;
    const int b_row = tid >> 5;
    const int b_col = (tid & 31) * 4;

    const float* Ag = A + (size_t)(by * BM + a_row) * K + a_col;
    const float* Bg = B + (size_t)b_row * N + bx * BN + b_col;

    unsigned int as_base = (unsigned int)__cvta_generic_to_shared(Asm);
    unsigned int bs_base = (unsigned int)__cvta_generic_to_shared(Bsm);

    float acc[2][8][4];
#pragma unroll
    for (int i = 0; i < 2; i++)
#pragma unroll
        for (int j = 0; j < 8; j++)
#pragma unroll
            for (int q = 0; q < 4; q++) acc[i][j][q] = 0.f;

    const int KT = K / BK;

    auto load_tile = [&](int buf, int k0) {
#pragma unroll
        for (int i = 0; i < 4; i++) {
            unsigned int dst = as_base + buf * (ASIZE * 4)
                             + ((a_row + i * 32) * AST + a_col) * 4;
            cp16(dst, Ag + (size_t)(i * 32) * K + k0);
        }
#pragma unroll
        for (int i = 0; i < 4; i++) {
            unsigned int dst = bs_base + buf * (BSIZE * 4)
                             + ((b_row + i * 8) * BST + b_col) * 4;
            cp16(dst, Bg + (size_t)(k0 + i * 8) * N);
        }
        asm volatile("cp.async.commit_group;\n");
    };

    load_tile(0, 0);

    for (int kt = 0; kt < KT; kt++) {
        const int cur = kt & 1;
        if (kt + 1 < KT) {
            load_tile(cur ^ 1, (kt + 1) * BK);
            asm volatile("cp.async.wait_group 1;\n");
        } else {
            asm volatile("cp.async.wait_group 0;\n");
        }
        __syncthreads();

        const float* As = Asm + cur * ASIZE;
        const float* Bs = Bsm + cur * BSIZE;
        const int m0 = warp_m * 32;
        const int n0 = warp_n * 64;

#pragma unroll
        for (int kk = 0; kk < 4; kk++) {
            unsigned int afh[2][4], afl[2][4];
#pragma unroll
            for (int mf = 0; mf < 2; mf++) {
                const float* ap = As + (m0 + mf * 16 + g) * AST + kk * 8 + tg;
                float v0 = ap[0];
                float v1 = ap[8 * AST];
                float v2 = ap[4];
                float v3 = ap[8 * AST + 4];
                afh[mf][0] = tf32_of(v0);
                afh[mf][1] = tf32_of(v1);
                afh[mf][2] = tf32_of(v2);
                afh[mf][3] = tf32_of(v3);
                afl[mf][0] = tf32_of(v0 - __uint_as_float(afh[mf][0]));
                afl[mf][1] = tf32_of(v1 - __uint_as_float(afh[mf][1]));
                afl[mf][2] = tf32_of(v2 - __uint_as_float(afh[mf][2]));
                afl[mf][3] = tf32_of(v3 - __uint_as_float(afh[mf][3]));
            }
            unsigned int bfh[8][2], bfl[8][2];
#pragma unroll
            for (int nf = 0; nf < 8; nf++) {
                const float* bp = Bs + (kk * 8 + tg) * BST + n0 + nf * 8 + g;
                float v0 = bp[0];
                float v1 = bp[4 * BST];
                bfh[nf][0] = tf32_of(v0);
                bfh[nf][1] = tf32_of(v1);
                bfl[nf][0] = tf32_of(v0 - __uint_as_float(bfh[nf][0]));
                bfl[nf][1] = tf32_of(v1 - __uint_as_float(bfh[nf][1]));
            }
#pragma unroll
            for (int mf = 0; mf < 2; mf++)
#pragma unroll
                for (int nf = 0; nf < 8; nf++) {
                    mma_tf32u(acc[mf][nf], afl[mf], bfh[nf]);
                    mma_tf32u(acc[mf][nf], afh[mf], bfl[nf]);
                    mma_tf32u(acc[mf][nf], afh[mf], bfh[nf]);
                }
        }
        __syncthreads();
    }

#pragma unroll
    for (int mf = 0; mf < 2; mf++) {
#pragma unroll
        for (int nf = 0; nf < 8; nf++) {
            int row = by * BM + warp_m * 32 + mf * 16 + g;
            int col = bx * BN + warp_n * 64 + nf * 8 + 2 * tg;
            float* cp = C + (size_t)row * N + col;
            *(float2*)cp               = make_float2(acc[mf][nf][0], acc[mf][nf][1]);
            *(float2*)(cp + 8 * N)     = make_float2(acc[mf][nf][2], acc[mf][nf][3]);
        }
    }
}

// ---------------------------------------------------------------------------
// RoPE (in-place over [4096, nheads*64])
// ---------------------------------------------------------------------------
__global__ void rope_kernel(float* __restrict__ T,
                            const float* __restrict__ cs,
                            const float* __restrict__ sn,
                            int nheads)
{
    int idx = blockIdx.x * blockDim.x + threadIdx.x;
    int total = NROWS * nheads * 32;
    if (idx >= total) return;
    int p   = idx & 31;
    int hh  = (idx >> 5) % nheads;
    int row = idx / (32 * nheads);

    float c1 = cs[row * HD + p];
    float c2 = cs[row * HD + p + 32];
    float s1 = sn[row * HD + p];
    float s2 = sn[row * HD + p + 32];

    float* base = T + (size_t)row * (nheads * HD) + hh * HD;
    float x1 = base[p];
    float x2 = base[p + 32];
    base[p]      = x1 * c1 - x2 * s1;
    base[p + 32] = x2 * c2 + x1 * s2;
}

// ---------------------------------------------------------------------------
// Tensor-core attention: one block = (b,h,16 q rows). 256 threads / 8 warps.
// QK^T and PV via 3xTF32 m16n8k8; softmax with __expf.
// smem: sQh/sQl [16][68], sKh/sKl [64][68] (reused for V), sS [16][1028]
// ---------------------------------------------------------------------------
#define QT 16
#define CH 64           // key chunk
#define PAD 68          // row stride for Q/K/V tiles (bank 4g+tg pattern)
#define SSP 1028        // score row stride
#define ATTN_SMEM ((2*QT*PAD + 2*CH*PAD + QT*SSP) * 4)   // 109312 B

__global__ __launch_bounds__(256) void attn_kernel(float* __restrict__ aw,
                                                   float* __restrict__ AO)
{
    extern __shared__ float sm[];
    float* sQh = sm;                       // 16*68
    float* sQl = sQh + QT * PAD;
    float* sKh = sQl + QT * PAD;           // 64*68 (K, then V)
    float* sKl = sKh + CH * PAD;
    float* sS  = sKl + CH * PAD;           // 16*1028

    const int qt = blockIdx.x & 63;
    const int bh = blockIdx.x >> 6;
    const int b  = bh / NH;
    const int h  = bh % NH;
    const int kvh = h / (NH / NKV);
    const int tid = threadIdx.x;
    const int w = tid >> 5, lane = tid & 31;
    const int g = lane >> 2, tg = lane & 3;
    const int q0 = qt * QT;
    const float scaling = 0.125f;

    // --- Q tile: split hi/lo into smem once ---
    for (int i = tid; i < QT * HD; i += 256) {
        int r = i >> 6, d = i & 63;
        float v = g_Q[(size_t)(b * SS + q0 + r) * QW + h * HD + d];
        unsigned int hi = tf32_of(v);
        sQh[r * PAD + d] = __uint_as_float(hi);
        sQl[r * PAD + d] = __uint_as_float(tf32_of(v - __uint_as_float(hi)));
    }

    // --- QK^T over 16 chunks of 64 keys ---
    const int nloc = w * 8 + g;            // this thread's key column (local)
    for (int kt = 0; kt < SS / CH; kt++) {
        __syncthreads();
        for (int i = tid; i < CH * HD; i += 256) {
            int kr = i >> 6, d = i & 63;
            float v = g_K[(size_t)(b * SS + kt * CH + kr) * KW + kvh * HD + d];
            unsigned int hi = tf32_of(v);
            sKh[kr * PAD + d] = __uint_as_float(hi);
            sKl[kr * PAD + d] = __uint_as_float(tf32_of(v - __uint_as_float(hi)));
        }
        __syncthreads();

        float acc[4] = {0.f, 0.f, 0.f, 0.f};
#pragma unroll
        for (int kk = 0; kk < 8; kk++) {
            const int c0 = kk * 8 + tg;
            unsigned int ah[4], al[4], bh_[2], bl_[2];
            ah[0] = __float_as_uint(sQh[g * PAD + c0]);
            ah[1] = __float_as_uint(sQh[(g + 8) * PAD + c0]);
            ah[2] = __float_as_uint(sQh[g * PAD + c0 + 4]);
            ah[3] = __float_as_uint(sQh[(g + 8) * PAD + c0 + 4]);
            al[0] = __float_as_uint(sQl[g * PAD + c0]);
            al[1] = __float_as_uint(sQl[(g + 8) * PAD + c0]);
            al[2] = __float_as_uint(sQl[g * PAD + c0 + 4]);
            al[3] = __float_as_uint(sQl[(g + 8) * PAD + c0 + 4]);
            bh_[0] = __float_as_uint(sKh[nloc * PAD + c0]);
            bh_[1] = __float_as_uint(sKh[nloc * PAD + c0 + 4]);
            bl_[0] = __float_as_uint(sKl[nloc * PAD + c0]);
            bl_[1] = __float_as_uint(sKl[nloc * PAD + c0 + 4]);
            mma_tf32u(acc, al, bh_);
            mma_tf32u(acc, ah, bl_);
            mma_tf32u(acc, ah, bh_);
        }
        // scores: rows g/g+8, cols kt*64 + w*8 + 2tg (+1)
        const int col = kt * CH + w * 8 + 2 * tg;
        const int r0q = q0 + g, r1q = q0 + g + 8;
        float v00 = acc[0] * scaling + ((col     > r0q) ? -1e9f : 0.f);
        float v01 = acc[1] * scaling + ((col + 1 > r0q) ? -1e9f : 0.f);
        float v10 = acc[2] * scaling + ((col     > r1q) ? -1e9f : 0.f);
        float v11 = acc[3] * scaling + ((col + 1 > r1q) ? -1e9f : 0.f);
        *(float2*)(sS + g * SSP + col)       = make_float2(v00, v01);
        *(float2*)(sS + (g + 8) * SSP + col) = make_float2(v10, v11);
    }
    __syncthreads();

    // --- softmax (8 warps x 2 rows), write aw ---
    {
        for (int rw = 0; rw < 2; rw++) {
            int r = w * 2 + rw;
            float* row = sS + r * SSP;
            float m = -INFINITY;
            for (int cc = lane; cc < SS; cc += 32) m = fmaxf(m, row[cc]);
#pragma unroll
            for (int o = 16; o; o >>= 1) m = fmaxf(m, __shfl_xor_sync(0xffffffffu, m, o));
            float ssum = 0.f;
            for (int cc = lane; cc < SS; cc += 32) {
                float p = __expf(row[cc] - m);
                row[cc] = p;
                ssum += p;
            }
#pragma unroll
            for (int o = 16; o; o >>= 1) ssum += __shfl_xor_sync(0xffffffffu, ssum, o);
            float inv = 1.f / ssum;
            float* awrow = aw + ((size_t)(bh * SS + q0 + r)) * SS;
            for (int cc = lane; cc < SS; cc += 32) {
                float p = row[cc] * inv;
                row[cc] = p;
                awrow[cc] = p;
            }
        }
    }

    // --- PV over 16 chunks of 64 keys ---
    float oacc[4] = {0.f, 0.f, 0.f, 0.f};
    for (int vt = 0; vt < SS / CH; vt++) {
        __syncthreads();
        for (int i = tid; i < CH * HD; i += 256) {
            int vr = i >> 6, d = i & 63;
            float v = g_V[(size_t)(b * SS + vt * CH + vr) * KW + kvh * HD + d];
            unsigned int hi = tf32_of(v);
            sKh[vr * PAD + d] = __uint_as_float(hi);
            sKl[vr * PAD + d] = __uint_as_float(tf32_of(v - __uint_as_float(hi)));
        }
        __syncthreads();

#pragma unroll
        for (int kk = 0; kk < 8; kk++) {
            const int kc = vt * CH + kk * 8 + tg;   // global key index
            float p0 = sS[g * SSP + kc];
            float p1 = sS[(g + 8) * SSP + kc];
            float p2 = sS[g * SSP + kc + 4];
            float p3 = sS[(g + 8) * SSP + kc + 4];
            unsigned int ah[4], al[4], bh_[2], bl_[2];
            ah[0] = tf32_of(p0); ah[1] = tf32_of(p1);
            ah[2] = tf32_of(p2); ah[3] = tf32_of(p3);
            al[0] = tf32_of(p0 - __uint_as_float(ah[0]));
            al[1] = tf32_of(p1 - __uint_as_float(ah[1]));
            al[2] = tf32_of(p2 - __uint_as_float(ah[2]));
            al[3] = tf32_of(p3 - __uint_as_float(ah[3]));
            const int krow = kk * 8 + tg;
            bh_[0] = __float_as_uint(sKh[krow * PAD + w * 8 + g]);
            bh_[1] = __float_as_uint(sKh[(krow + 4) * PAD + w * 8 + g]);
            bl_[0] = __float_as_uint(sKl[krow * PAD + w * 8 + g]);
            bl_[1] = __float_as_uint(sKl[(krow + 4) * PAD + w * 8 + g]);
            mma_tf32u(oacc, al, bh_);
            mma_tf32u(oacc, ah, bl_);
            mma_tf32u(oacc, ah, bh_);
        }
    }

    // write AO: rows q0+g / q0+g+8, cols h*HD + w*8 + 2tg (+1)
    {
        float* o0 = AO + (size_t)(b * SS + q0 + g) * QW + h * HD + w * 8 + 2 * tg;
        float* o1 = AO + (size_t)(b * SS + q0 + g + 8) * QW + h * HD + w * 8 + 2 * tg;
        *(float2*)o0 = make_float2(oacc[0], oacc[1]);
        *(float2*)o1 = make_float2(oacc[2], oacc[3]);
    }
}

// ---------------------------------------------------------------------------
// Launch
// ---------------------------------------------------------------------------
extern "C" void kernel_launch(void* const* d_in, const int* in_sizes, int n_in,
                              void* d_out, int out_size)
{
    const float* x    = (const float*)d_in[0];
    const float* cs   = (const float*)d_in[1];
    const float* sn   = (const float*)d_in[2];
    // d_in[3] = attention_mask (pure causal; reproduced analytically)
    const float* Wq   = (const float*)d_in[4];
    const float* Wk   = (const float*)d_in[5];
    const float* Wv   = (const float*)d_in[6];
    const float* Wo   = (const float*)d_in[7];

    float* out = (float*)d_out;
    float* aw  = out + (size_t)NROWS * HH;

    float *Qp, *Kp, *Vp, *AOp;
    cudaGetSymbolAddress((void**)&Qp,  g_Q);
    cudaGetSymbolAddress((void**)&Kp,  g_K);
    cudaGetSymbolAddress((void**)&Vp,  g_V);
    cudaGetSymbolAddress((void**)&AOp, g_AO);

    cudaFuncSetAttribute(attn_kernel, cudaFuncAttributeMaxDynamicSharedMemorySize, ATTN_SMEM);
    cudaFuncSetAttribute(gemm_tf32, cudaFuncAttributeMaxDynamicSharedMemorySize, GEMM_SMEM);

    // Projections (3xTF32 tensor cores)
    {
        dim3 g(QW / BN, NROWS / BM);
        gemm_tf32<<<g, 256, GEMM_SMEM>>>(x, Wq, Qp, NROWS, QW, HH);
    }
    {
        dim3 g(KW / BN, NROWS / BM);
        gemm_tf32<<<g, 256, GEMM_SMEM>>>(x, Wk, Kp, NROWS, KW, HH);
        gemm_tf32<<<g, 256, GEMM_SMEM>>>(x, Wv, Vp, NROWS, KW, HH);
    }

    // RoPE
    {
        int totq = NROWS * NH * 32;
        rope_kernel<<<(totq + 255) / 256, 256>>>(Qp, cs, sn, NH);
        int totk = NROWS * NKV * 32;
        rope_kernel<<<(totk + 255) / 256, 256>>>(Kp, cs, sn, NKV);
    }

    // Attention (+ aw output)
    {
        int grid = BB * NH * (SS / QT);
        attn_kernel<<<grid, 256, ATTN_SMEM>>>(aw, AOp);
    }

    // Output projection
    {
        dim3 g(HH / BN, NROWS / BM);
        gemm_tf32<<<g, 256, GEMM_SMEM>>>(AOp, Wo, out, NROWS, HH, QW);
    }

    (void)in_sizes; (void)n_in; (void)out_size;
}

// round 9
// speedup vs baseline: 2.0819x; 1.5180x over previous
#include <cuda_runtime.h>
#include <cuda_bf16.h>
#include <cstdint>
#include <math.h>

// Problem constants
#define BB 4
#define SS 1024
#define HH 2048
#define NH 32
#define NKV 8
#define HD 64
#define NROWS (BB*SS)          // 4096
#define QW (NH*HD)             // 2048
#define KW (NKV*HD)            // 512

// Scratch (device globals; no allocation allowed)
__device__ float g_Q[NROWS * QW];
__device__ float g_K[NROWS * KW];
__device__ float g_V[NROWS * KW];
__device__ float g_AO[NROWS * QW];

// ---------------------------------------------------------------------------
// mma helpers
// ---------------------------------------------------------------------------
__device__ __forceinline__ void cp16(unsigned int dst, const void* src) {
    asm volatile("cp.async.cg.shared.global [%0], [%1], 16;\n" :: "r"(dst), "l"(src));
}

__device__ __forceinline__ unsigned int tf32_of(float x) {
    unsigned int r;
    asm("cvt.rna.tf32.f32 %0, %1;\n" : "=r"(r) : "f"(x));
    return r;
}

__device__ __forceinline__ void mma_tf32u(float* c, const unsigned int* a,
                                          const unsigned int* b) {
    asm volatile(
        "mma.sync.aligned.m16n8k8.row.col.f32.tf32.tf32.f32 "
        "{%0,%1,%2,%3}, {%4,%5,%6,%7}, {%8,%9}, {%0,%1,%2,%3};\n"
        : "+f"(c[0]), "+f"(c[1]), "+f"(c[2]), "+f"(c[3])
        : "r"(a[0]), "r"(a[1]), "r"(a[2]), "r"(a[3]),
          "r"(b[0]), "r"(b[1]));
}

// ---------------------------------------------------------------------------
// 3xTF32 tensor-core GEMM: C[M,N] = A[M,K] @ B[K,N] (unchanged)
// ---------------------------------------------------------------------------
#define BM 128
#define BN 128
#define BK 32
#define AST 36
#define BST 136
#define ASIZE (BM*AST)
#define BSIZE (BK*BST)
#define GEMM_SMEM ((2*ASIZE + 2*BSIZE)*4)

__global__ __launch_bounds__(256) void gemm_tf32(
    const float* __restrict__ A, const float* __restrict__ B,
    float* __restrict__ C, int M, int N, int K)
{
    extern __shared__ float smem[];
    float* Asm = smem;
    float* Bsm = smem + 2 * ASIZE;

    const int tid = threadIdx.x;
    const int wid = tid >> 5, lane = tid & 31;
    const int g = lane >> 2, tg = lane & 3;
    const int warp_m = wid & 3;
    const int warp_n = wid >> 2;
    const int bx = blockIdx.x, by = blockIdx.y;

    const int a_row = tid >> 3;
    const int a_col = (tid & 7) * 4;
    const int b_row = tid >> 5;
    const int b_col = (tid & 31) * 4;

    const float* Ag = A + (size_t)(by * BM + a_row) * K + a_col;
    const float* Bg = B + (size_t)b_row * N + bx * BN + b_col;

    unsigned int as_base = (unsigned int)__cvta_generic_to_shared(Asm);
    unsigned int bs_base = (unsigned int)__cvta_generic_to_shared(Bsm);

    float acc[2][8][4];
#pragma unroll
    for (int i = 0; i < 2; i++)
#pragma unroll
        for (int j = 0; j < 8; j++)
#pragma unroll
            for (int q = 0; q < 4; q++) acc[i][j][q] = 0.f;

    const int KT = K / BK;

    auto load_tile = [&](int buf, int k0) {
#pragma unroll
        for (int i = 0; i < 4; i++) {
            unsigned int dst = as_base + buf * (ASIZE * 4)
                             + ((a_row + i * 32) * AST + a_col) * 4;
            cp16(dst, Ag + (size_t)(i * 32) * K + k0);
        }
#pragma unroll
        for (int i = 0; i < 4; i++) {
            unsigned int dst = bs_base + buf * (BSIZE * 4)
                             + ((b_row + i * 8) * BST + b_col) * 4;
            cp16(dst, Bg + (size_t)(k0 + i * 8) * N);
        }
        asm volatile("cp.async.commit_group;\n");
    };

    load_tile(0, 0);

    for (int kt = 0; kt < KT; kt++) {
        const int cur = kt & 1;
        if (kt + 1 < KT) {
            load_tile(cur ^ 1, (kt + 1) * BK);
            asm volatile("cp.async.wait_group 1;\n");
        } else {
            asm volatile("cp.async.wait_group 0;\n");
        }
        __syncthreads();

        const float* As = Asm + cur * ASIZE;
        const float* Bs = Bsm + cur * BSIZE;
        const int m0 = warp_m * 32;
        const int n0 = warp_n * 64;

#pragma unroll
        for (int kk = 0; kk < 4; kk++) {
            unsigned int afh[2][4], afl[2][4];
#pragma unroll
            for (int mf = 0; mf < 2; mf++) {
                const float* ap = As + (m0 + mf * 16 + g) * AST + kk * 8 + tg;
                float v0 = ap[0];
                float v1 = ap[8 * AST];
                float v2 = ap[4];
                float v3 = ap[8 * AST + 4];
                afh[mf][0] = tf32_of(v0);
                afh[mf][1] = tf32_of(v1);
                afh[mf][2] = tf32_of(v2);
                afh[mf][3] = tf32_of(v3);
                afl[mf][0] = tf32_of(v0 - __uint_as_float(afh[mf][0]));
                afl[mf][1] = tf32_of(v1 - __uint_as_float(afh[mf][1]));
                afl[mf][2] = tf32_of(v2 - __uint_as_float(afh[mf][2]));
                afl[mf][3] = tf32_of(v3 - __uint_as_float(afh[mf][3]));
            }
            unsigned int bfh[8][2], bfl[8][2];
#pragma unroll
            for (int nf = 0; nf < 8; nf++) {
                const float* bp = Bs + (kk * 8 + tg) * BST + n0 + nf * 8 + g;
                float v0 = bp[0];
                float v1 = bp[4 * BST];
                bfh[nf][0] = tf32_of(v0);
                bfh[nf][1] = tf32_of(v1);
                bfl[nf][0] = tf32_of(v0 - __uint_as_float(bfh[nf][0]));
                bfl[nf][1] = tf32_of(v1 - __uint_as_float(bfh[nf][1]));
            }
#pragma unroll
            for (int mf = 0; mf < 2; mf++)
#pragma unroll
                for (int nf = 0; nf < 8; nf++) {
                    mma_tf32u(acc[mf][nf], afl[mf], bfh[nf]);
                    mma_tf32u(acc[mf][nf], afh[mf], bfl[nf]);
                    mma_tf32u(acc[mf][nf], afh[mf], bfh[nf]);
                }
        }
        __syncthreads();
    }

#pragma unroll
    for (int mf = 0; mf < 2; mf++) {
#pragma unroll
        for (int nf = 0; nf < 8; nf++) {
            int row = by * BM + warp_m * 32 + mf * 16 + g;
            int col = bx * BN + warp_n * 64 + nf * 8 + 2 * tg;
            float* cp = C + (size_t)row * N + col;
            *(float2*)cp               = make_float2(acc[mf][nf][0], acc[mf][nf][1]);
            *(float2*)(cp + 8 * N)     = make_float2(acc[mf][nf][2], acc[mf][nf][3]);
        }
    }
}

// ---------------------------------------------------------------------------
// RoPE (in-place over [4096, nheads*64])
// ---------------------------------------------------------------------------
__global__ void rope_kernel(float* __restrict__ T,
                            const float* __restrict__ cs,
                            const float* __restrict__ sn,
                            int nheads)
{
    int idx = blockIdx.x * blockDim.x + threadIdx.x;
    int total = NROWS * nheads * 32;
    if (idx >= total) return;
    int p   = idx & 31;
    int hh  = (idx >> 5) % nheads;
    int row = idx / (32 * nheads);

    float c1 = cs[row * HD + p];
    float c2 = cs[row * HD + p + 32];
    float s1 = sn[row * HD + p];
    float s2 = sn[row * HD + p + 32];

    float* base = T + (size_t)row * (nheads * HD) + hh * HD;
    float x1 = base[p];
    float x2 = base[p + 32];
    base[p]      = x1 * c1 - x2 * s1;
    base[p + 32] = x2 * c2 + x1 * s2;
}

// ---------------------------------------------------------------------------
// Tensor-core attention: one block = (b,h,32 q rows). 512 threads / 16 warps.
// Causal skip: only nch = ceil((q0+32)/64) key chunks processed; rest -> aw=0.
// smem: sQh/sQl [32][68], sKh/sKl [64][68] (K then V), sS [32][1028]
// ---------------------------------------------------------------------------
#define QT 32
#define CH 64
#define PAD 68
#define SSP 1028
#define NQT (SS/QT)     // 32
#define ATTN_SMEM ((2*QT*PAD + 2*CH*PAD + QT*SSP) * 4)   // 183808 B

__global__ __launch_bounds__(512) void attn_kernel(float* __restrict__ aw,
                                                   float* __restrict__ AO)
{
    extern __shared__ float sm[];
    float* sQh = sm;                       // 32*68
    float* sQl = sQh + QT * PAD;
    float* sKh = sQl + QT * PAD;           // 64*68 (K, then V)
    float* sKl = sKh + CH * PAD;
    float* sS  = sKl + CH * PAD;           // 32*1028

    const int qt = blockIdx.x & (NQT - 1);
    const int bh = blockIdx.x / NQT;
    const int b  = bh / NH;
    const int h  = bh % NH;
    const int kvh = h / (NH / NKV);
    const int tid = threadIdx.x;
    const int w = tid >> 5, lane = tid & 31;
    const int g = lane >> 2, tg = lane & 3;
    const int mq = (w >> 3) * 16;          // 0 or 16
    const int nc = w & 7;                  // 0..7
    const int q0 = qt * QT;
    const float scaling = 0.125f;

    const int nch  = (q0 + QT + CH - 1) / CH;  // chunks needed (causal)
    const int klim = nch * CH;

    // --- Q tile: split hi/lo into smem once ---
    for (int i = tid; i < QT * HD; i += 512) {
        int r = i >> 6, d = i & 63;
        float v = g_Q[(size_t)(b * SS + q0 + r) * QW + h * HD + d];
        unsigned int hi = tf32_of(v);
        sQh[r * PAD + d] = __uint_as_float(hi);
        sQl[r * PAD + d] = __uint_as_float(tf32_of(v - __uint_as_float(hi)));
    }

    // --- QK^T over nch chunks of 64 keys ---
    for (int kt = 0; kt < nch; kt++) {
        __syncthreads();
        for (int i = tid; i < CH * HD; i += 512) {
            int kr = i >> 6, d = i & 63;
            float v = g_K[(size_t)(b * SS + kt * CH + kr) * KW + kvh * HD + d];
            unsigned int hi = tf32_of(v);
            sKh[kr * PAD + d] = __uint_as_float(hi);
            sKl[kr * PAD + d] = __uint_as_float(tf32_of(v - __uint_as_float(hi)));
        }
        __syncthreads();

        float acc[4] = {0.f, 0.f, 0.f, 0.f};
        const int nloc = nc * 8 + g;
#pragma unroll
        for (int kk = 0; kk < 8; kk++) {
            const int c0 = kk * 8 + tg;
            unsigned int ah[4], al[4], bh_[2], bl_[2];
            ah[0] = __float_as_uint(sQh[(mq + g) * PAD + c0]);
            ah[1] = __float_as_uint(sQh[(mq + g + 8) * PAD + c0]);
            ah[2] = __float_as_uint(sQh[(mq + g) * PAD + c0 + 4]);
            ah[3] = __float_as_uint(sQh[(mq + g + 8) * PAD + c0 + 4]);
            al[0] = __float_as_uint(sQl[(mq + g) * PAD + c0]);
            al[1] = __float_as_uint(sQl[(mq + g + 8) * PAD + c0]);
            al[2] = __float_as_uint(sQl[(mq + g) * PAD + c0 + 4]);
            al[3] = __float_as_uint(sQl[(mq + g + 8) * PAD + c0 + 4]);
            bh_[0] = __float_as_uint(sKh[nloc * PAD + c0]);
            bh_[1] = __float_as_uint(sKh[nloc * PAD + c0 + 4]);
            bl_[0] = __float_as_uint(sKl[nloc * PAD + c0]);
            bl_[1] = __float_as_uint(sKl[nloc * PAD + c0 + 4]);
            mma_tf32u(acc, al, bh_);
            mma_tf32u(acc, ah, bl_);
            mma_tf32u(acc, ah, bh_);
        }
        const int col = kt * CH + nc * 8 + 2 * tg;
        const int r0q = q0 + mq + g, r1q = q0 + mq + g + 8;
        float v00 = acc[0] * scaling + ((col     > r0q) ? -1e9f : 0.f);
        float v01 = acc[1] * scaling + ((col + 1 > r0q) ? -1e9f : 0.f);
        float v10 = acc[2] * scaling + ((col     > r1q) ? -1e9f : 0.f);
        float v11 = acc[3] * scaling + ((col + 1 > r1q) ? -1e9f : 0.f);
        *(float2*)(sS + (mq + g) * SSP + col)     = make_float2(v00, v01);
        *(float2*)(sS + (mq + g + 8) * SSP + col) = make_float2(v10, v11);
    }
    __syncthreads();

    // --- softmax (16 warps x 2 rows of 32), cols < klim; aw zero-fill beyond ---
    {
        for (int rw = 0; rw < 2; rw++) {
            int r = w * 2 + rw;
            float* row = sS + r * SSP;
            float m = -INFINITY;
            for (int cc = lane; cc < klim; cc += 32) m = fmaxf(m, row[cc]);
#pragma unroll
            for (int o = 16; o; o >>= 1) m = fmaxf(m, __shfl_xor_sync(0xffffffffu, m, o));
            float ssum = 0.f;
            for (int cc = lane; cc < klim; cc += 32) {
                float p = __expf(row[cc] - m);
                row[cc] = p;
                ssum += p;
            }
#pragma unroll
            for (int o = 16; o; o >>= 1) ssum += __shfl_xor_sync(0xffffffffu, ssum, o);
            float inv = 1.f / ssum;
            float* awrow = aw + ((size_t)(bh * SS + q0 + r)) * SS;
            for (int cc = lane; cc < klim; cc += 32) {
                float p = row[cc] * inv;
                row[cc] = p;
                awrow[cc] = p;
            }
            for (int cc = klim + lane; cc < SS; cc += 32) awrow[cc] = 0.f;
        }
    }

    // --- PV over nch chunks ---
    float oacc[4] = {0.f, 0.f, 0.f, 0.f};
    for (int vt = 0; vt < nch; vt++) {
        __syncthreads();
        for (int i = tid; i < CH * HD; i += 512) {
            int vr = i >> 6, d = i & 63;
            float v = g_V[(size_t)(b * SS + vt * CH + vr) * KW + kvh * HD + d];
            unsigned int hi = tf32_of(v);
            sKh[vr * PAD + d] = __uint_as_float(hi);
            sKl[vr * PAD + d] = __uint_as_float(tf32_of(v - __uint_as_float(hi)));
        }
        __syncthreads();

#pragma unroll
        for (int kk = 0; kk < 8; kk++) {
            const int kc = vt * CH + kk * 8 + tg;
            float p0 = sS[(mq + g) * SSP + kc];
            float p1 = sS[(mq + g + 8) * SSP + kc];
            float p2 = sS[(mq + g) * SSP + kc + 4];
            float p3 = sS[(mq + g + 8) * SSP + kc + 4];
            unsigned int ah[4], al[4], bh_[2], bl_[2];
            ah[0] = tf32_of(p0); ah[1] = tf32_of(p1);
            ah[2] = tf32_of(p2); ah[3] = tf32_of(p3);
            al[0] = tf32_of(p0 - __uint_as_float(ah[0]));
            al[1] = tf32_of(p1 - __uint_as_float(ah[1]));
            al[2] = tf32_of(p2 - __uint_as_float(ah[2]));
            al[3] = tf32_of(p3 - __uint_as_float(ah[3]));
            const int krow = kk * 8 + tg;
            bh_[0] = __float_as_uint(sKh[krow * PAD + nc * 8 + g]);
            bh_[1] = __float_as_uint(sKh[(krow + 4) * PAD + nc * 8 + g]);
            bl_[0] = __float_as_uint(sKl[krow * PAD + nc * 8 + g]);
            bl_[1] = __float_as_uint(sKl[(krow + 4) * PAD + nc * 8 + g]);
            mma_tf32u(oacc, al, bh_);
            mma_tf32u(oacc, ah, bl_);
            mma_tf32u(oacc, ah, bh_);
        }
    }

    // write AO
    {
        float* o0 = AO + (size_t)(b * SS + q0 + mq + g) * QW + h * HD + nc * 8 + 2 * tg;
        float* o1 = AO + (size_t)(b * SS + q0 + mq + g + 8) * QW + h * HD + nc * 8 + 2 * tg;
        *(float2*)o0 = make_float2(oacc[0], oacc[1]);
        *(float2*)o1 = make_float2(oacc[2], oacc[3]);
    }
}

// ---------------------------------------------------------------------------
// Launch
// ---------------------------------------------------------------------------
extern "C" void kernel_launch(void* const* d_in, const int* in_sizes, int n_in,
                              void* d_out, int out_size)
{
    const float* x    = (const float*)d_in[0];
    const float* cs   = (const float*)d_in[1];
    const float* sn   = (const float*)d_in[2];
    // d_in[3] = attention_mask (pure causal; reproduced analytically)
    const float* Wq   = (const float*)d_in[4];
    const float* Wk   = (const float*)d_in[5];
    const float* Wv   = (const float*)d_in[6];
    const float* Wo   = (const float*)d_in[7];

    float* out = (float*)d_out;
    float* aw  = out + (size_t)NROWS * HH;

    float *Qp, *Kp, *Vp, *AOp;
    cudaGetSymbolAddress((void**)&Qp,  g_Q);
    cudaGetSymbolAddress((void**)&Kp,  g_K);
    cudaGetSymbolAddress((void**)&Vp,  g_V);
    cudaGetSymbolAddress((void**)&AOp, g_AO);

    cudaFuncSetAttribute(attn_kernel, cudaFuncAttributeMaxDynamicSharedMemorySize, ATTN_SMEM);
    cudaFuncSetAttribute(gemm_tf32, cudaFuncAttributeMaxDynamicSharedMemorySize, GEMM_SMEM);

    // Projections (3xTF32 tensor cores)
    {
        dim3 g(QW / BN, NROWS / BM);
        gemm_tf32<<<g, 256, GEMM_SMEM>>>(x, Wq, Qp, NROWS, QW, HH);
    }
    {
        dim3 g(KW / BN, NROWS / BM);
        gemm_tf32<<<g, 256, GEMM_SMEM>>>(x, Wk, Kp, NROWS, KW, HH);
        gemm_tf32<<<g, 256, GEMM_SMEM>>>(x, Wv, Vp, NROWS, KW, HH);
    }

    // RoPE
    {
        int totq = NROWS * NH * 32;
        rope_kernel<<<(totq + 255) / 256, 256>>>(Qp, cs, sn, NH);
        int totk = NROWS * NKV * 32;
        rope_kernel<<<(totk + 255) / 256, 256>>>(Kp, cs, sn, NKV);
    }

    // Attention (+ aw output)
    {
        int grid = BB * NH * NQT;   // 4096
        attn_kernel<<<grid, 512, ATTN_SMEM>>>(aw, AOp);
    }

    // Output projection
    {
        dim3 g(HH / BN, NROWS / BM);
        gemm_tf32<<<g, 256, GEMM_SMEM>>>(AOp, Wo, out, NROWS, HH, QW);
    }

    (void)in_sizes; (void)n_in; (void)out_size;
}

// round 10
// speedup vs baseline: 2.6848x; 1.2896x over previous
#include <cuda_runtime.h>
#include <cuda_bf16.h>
#include <cstdint>
#include <math.h>

// Problem constants
#define BB 4
#define SS 1024
#define HH 2048
#define NH 32
#define NKV 8
#define HD 64
#define NROWS (BB*SS)          // 4096
#define QW (NH*HD)             // 2048
#define KW (NKV*HD)            // 512

// Scratch (device globals; no allocation allowed)
__device__ float g_Q[NROWS * QW];
__device__ float g_K[NROWS * KW];
__device__ float g_V[NROWS * KW];
__device__ __nv_bfloat16 g_xh[NROWS * HH],  g_xl[NROWS * HH];
__device__ __nv_bfloat16 g_Wqh[QW * HH],    g_Wql[QW * HH];     // [N][K]
__device__ __nv_bfloat16 g_Wkh[KW * HH],    g_Wkl[KW * HH];     // [N][K]
__device__ __nv_bfloat16 g_Wvh[KW * HH],    g_Wvl[KW * HH];     // [N][K]
__device__ __nv_bfloat16 g_Woh[HH * QW],    g_Wol[HH * QW];     // [N][K]
__device__ __nv_bfloat16 g_AOh[NROWS * QW], g_AOl[NROWS * QW];

// ---------------------------------------------------------------------------
// helpers
// ---------------------------------------------------------------------------
__device__ __forceinline__ void cp16(unsigned int dst, const void* src) {
    asm volatile("cp.async.cg.shared.global [%0], [%1], 16;\n" :: "r"(dst), "l"(src));
}

__device__ __forceinline__ unsigned int tf32_of(float x) {
    unsigned int r;
    asm("cvt.rna.tf32.f32 %0, %1;\n" : "=r"(r) : "f"(x));
    return r;
}

__device__ __forceinline__ void mma_tf32u(float* c, const unsigned int* a,
                                          const unsigned int* b) {
    asm volatile(
        "mma.sync.aligned.m16n8k8.row.col.f32.tf32.tf32.f32 "
        "{%0,%1,%2,%3}, {%4,%5,%6,%7}, {%8,%9}, {%0,%1,%2,%3};\n"
        : "+f"(c[0]), "+f"(c[1]), "+f"(c[2]), "+f"(c[3])
        : "r"(a[0]), "r"(a[1]), "r"(a[2]), "r"(a[3]),
          "r"(b[0]), "r"(b[1]));
}

__device__ __forceinline__ void mma_bf16(float* c, const unsigned int* a,
                                         const unsigned int* b) {
    asm volatile(
        "mma.sync.aligned.m16n8k16.row.col.f32.bf16.bf16.f32 "
        "{%0,%1,%2,%3}, {%4,%5,%6,%7}, {%8,%9}, {%0,%1,%2,%3};\n"
        : "+f"(c[0]), "+f"(c[1]), "+f"(c[2]), "+f"(c[3])
        : "r"(a[0]), "r"(a[1]), "r"(a[2]), "r"(a[3]),
          "r"(b[0]), "r"(b[1]));
}

// ---------------------------------------------------------------------------
// Split kernels: fp32 -> bf16 hi/lo (plain + transposing)
// ---------------------------------------------------------------------------
__global__ void split_kernel(const float* __restrict__ src,
                             __nv_bfloat16* __restrict__ h,
                             __nv_bfloat16* __restrict__ l, int n)
{
    int i = blockIdx.x * blockDim.x + threadIdx.x;
    if (i >= n) return;
    float v = src[i];
    __nv_bfloat16 hb = __float2bfloat16(v);
    h[i] = hb;
    l[i] = __float2bfloat16(v - __bfloat162float(hb));
}

// src [K][N] fp32 -> dst [N][K] bf16 hi/lo
__global__ void splitT_kernel(const float* __restrict__ src,
                              __nv_bfloat16* __restrict__ h,
                              __nv_bfloat16* __restrict__ l, int K, int N)
{
    __shared__ float t[32][33];
    int k0 = blockIdx.y * 32, n0 = blockIdx.x * 32;
    int tx = threadIdx.x, ty = threadIdx.y;   // 32x8
#pragma unroll
    for (int i = 0; i < 32; i += 8)
        t[ty + i][tx] = src[(size_t)(k0 + ty + i) * N + n0 + tx];
    __syncthreads();
#pragma unroll
    for (int i = 0; i < 32; i += 8) {
        float v = t[tx][ty + i];
        __nv_bfloat16 hb = __float2bfloat16(v);
        size_t o = (size_t)(n0 + ty + i) * K + k0 + tx;
        h[o] = hb;
        l[o] = __float2bfloat16(v - __bfloat162float(hb));
    }
}

// ---------------------------------------------------------------------------
// 3xBF16 tensor-core GEMM: C[M,N] = A[M,K] @ B[N,K]^T (both k-contiguous bf16
// hi/lo). 128x128x32 tile, 256 threads, warp tile 32x64, cp.async double buf.
// ---------------------------------------------------------------------------
#define HST 40               // smem row stride (bf16 elems) for 32-k tiles
#define HTILE (128*HST)      // 5120 elems per operand-half tile
#define HGEMM_SMEM (2*4*HTILE*2)   // 81920 B

__global__ __launch_bounds__(256) void gemm_bf16_3(
    const __nv_bfloat16* __restrict__ Ah, const __nv_bfloat16* __restrict__ Al,
    const __nv_bfloat16* __restrict__ Bh, const __nv_bfloat16* __restrict__ Bl,
    float* __restrict__ C, int M, int N, int K)
{
    extern __shared__ __nv_bfloat16 hsm[];
    const int tid = threadIdx.x;
    const int wid = tid >> 5, lane = tid & 31;
    const int g = lane >> 2, tg = lane & 3;
    const int warp_m = wid & 3;
    const int warp_n = wid >> 2;
    const int bx = blockIdx.x, by = blockIdx.y;

    unsigned int sbase = (unsigned int)__cvta_generic_to_shared(hsm);

    float acc[2][8][4];
#pragma unroll
    for (int i = 0; i < 2; i++)
#pragma unroll
        for (int j = 0; j < 8; j++)
#pragma unroll
            for (int q = 0; q < 4; q++) acc[i][j][q] = 0.f;

    const int KT = K / 32;

    // per tile: 128 rows x 32 k x 2B = 4 chunks of 16B per row
    auto load_tile = [&](int buf, int k0) {
        unsigned int b0 = sbase + buf * (4 * HTILE * 2);
#pragma unroll
        for (int i = 0; i < 2; i++) {
            int c = i * 256 + tid;
            int row = c >> 2, ch = c & 3;
            unsigned int soff = (row * HST + ch * 8) * 2;
            size_t aoff = (size_t)(by * 128 + row) * K + k0 + ch * 8;
            size_t boff = (size_t)(bx * 128 + row) * K + k0 + ch * 8;
            cp16(b0 + soff,                 Ah + aoff);
            cp16(b0 + HTILE * 2 + soff,     Al + aoff);
            cp16(b0 + 2 * HTILE * 2 + soff, Bh + boff);
            cp16(b0 + 3 * HTILE * 2 + soff, Bl + boff);
        }
        asm volatile("cp.async.commit_group;\n");
    };

    load_tile(0, 0);

    for (int kt = 0; kt < KT; kt++) {
        const int cur = kt & 1;
        if (kt + 1 < KT) {
            load_tile(cur ^ 1, (kt + 1) * 32);
            asm volatile("cp.async.wait_group 1;\n");
        } else {
            asm volatile("cp.async.wait_group 0;\n");
        }
        __syncthreads();

        const __nv_bfloat16* sAh = hsm + cur * 4 * HTILE;
        const __nv_bfloat16* sAl = sAh + HTILE;
        const __nv_bfloat16* sBh = sAl + HTILE;
        const __nv_bfloat16* sBl = sBh + HTILE;
        const int m0 = warp_m * 32;
        const int n0 = warp_n * 64;

#pragma unroll
        for (int kk = 0; kk < 2; kk++) {
            unsigned int ah[2][4], al_[2][4];
#pragma unroll
            for (int mf = 0; mf < 2; mf++) {
                int base = (m0 + mf * 16 + g) * HST + kk * 16 + 2 * tg;
                ah[mf][0] = *(const unsigned int*)&sAh[base];
                ah[mf][1] = *(const unsigned int*)&sAh[base + 8 * HST];
                ah[mf][2] = *(const unsigned int*)&sAh[base + 8];
                ah[mf][3] = *(const unsigned int*)&sAh[base + 8 * HST + 8];
                al_[mf][0] = *(const unsigned int*)&sAl[base];
                al_[mf][1] = *(const unsigned int*)&sAl[base + 8 * HST];
                al_[mf][2] = *(const unsigned int*)&sAl[base + 8];
                al_[mf][3] = *(const unsigned int*)&sAl[base + 8 * HST + 8];
            }
#pragma unroll
            for (int nf = 0; nf < 8; nf++) {
                int bb = (n0 + nf * 8 + g) * HST + kk * 16 + 2 * tg;
                unsigned int bh2[2], bl2[2];
                bh2[0] = *(const unsigned int*)&sBh[bb];
                bh2[1] = *(const unsigned int*)&sBh[bb + 8];
                bl2[0] = *(const unsigned int*)&sBl[bb];
                bl2[1] = *(const unsigned int*)&sBl[bb + 8];
#pragma unroll
                for (int mf = 0; mf < 2; mf++) {
                    mma_bf16(acc[mf][nf], ah[mf], bl2);
                    mma_bf16(acc[mf][nf], al_[mf], bh2);
                    mma_bf16(acc[mf][nf], ah[mf], bh2);
                }
            }
        }
        __syncthreads();
    }

#pragma unroll
    for (int mf = 0; mf < 2; mf++) {
#pragma unroll
        for (int nf = 0; nf < 8; nf++) {
            int row = by * 128 + warp_m * 32 + mf * 16 + g;
            int col = bx * 128 + warp_n * 64 + nf * 8 + 2 * tg;
            float* cp = C + (size_t)row * N + col;
            *(float2*)cp           = make_float2(acc[mf][nf][0], acc[mf][nf][1]);
            *(float2*)(cp + 8 * N) = make_float2(acc[mf][nf][2], acc[mf][nf][3]);
        }
    }
}

// ---------------------------------------------------------------------------
// RoPE (in-place over [4096, nheads*64])
// ---------------------------------------------------------------------------
__global__ void rope_kernel(float* __restrict__ T,
                            const float* __restrict__ cs,
                            const float* __restrict__ sn,
                            int nheads)
{
    int idx = blockIdx.x * blockDim.x + threadIdx.x;
    int total = NROWS * nheads * 32;
    if (idx >= total) return;
    int p   = idx & 31;
    int hh  = (idx >> 5) % nheads;
    int row = idx / (32 * nheads);

    float c1 = cs[row * HD + p];
    float c2 = cs[row * HD + p + 32];
    float s1 = sn[row * HD + p];
    float s2 = sn[row * HD + p + 32];

    float* base = T + (size_t)row * (nheads * HD) + hh * HD;
    float x1 = base[p];
    float x2 = base[p + 32];
    base[p]      = x1 * c1 - x2 * s1;
    base[p + 32] = x2 * c2 + x1 * s2;
}

// ---------------------------------------------------------------------------
// Tensor-core attention (R9 layout) — epilogue now writes AO as bf16 hi/lo.
// ---------------------------------------------------------------------------
#define QT 32
#define CH 64
#define PAD 68
#define SSP 1028
#define NQT (SS/QT)     // 32
#define ATTN_SMEM ((2*QT*PAD + 2*CH*PAD + QT*SSP) * 4)   // 183808 B

__global__ __launch_bounds__(512) void attn_kernel(float* __restrict__ aw)
{
    extern __shared__ float sm[];
    float* sQh = sm;
    float* sQl = sQh + QT * PAD;
    float* sKh = sQl + QT * PAD;
    float* sKl = sKh + CH * PAD;
    float* sS  = sKl + CH * PAD;

    const int qt = blockIdx.x & (NQT - 1);
    const int bh = blockIdx.x / NQT;
    const int b  = bh / NH;
    const int h  = bh % NH;
    const int kvh = h / (NH / NKV);
    const int tid = threadIdx.x;
    const int w = tid >> 5, lane = tid & 31;
    const int g = lane >> 2, tg = lane & 3;
    const int mq = (w >> 3) * 16;
    const int nc = w & 7;
    const int q0 = qt * QT;
    const float scaling = 0.125f;

    const int nch  = (q0 + QT + CH - 1) / CH;
    const int klim = nch * CH;

    for (int i = tid; i < QT * HD; i += 512) {
        int r = i >> 6, d = i & 63;
        float v = g_Q[(size_t)(b * SS + q0 + r) * QW + h * HD + d];
        unsigned int hi = tf32_of(v);
        sQh[r * PAD + d] = __uint_as_float(hi);
        sQl[r * PAD + d] = __uint_as_float(tf32_of(v - __uint_as_float(hi)));
    }

    for (int kt = 0; kt < nch; kt++) {
        __syncthreads();
        for (int i = tid; i < CH * HD; i += 512) {
            int kr = i >> 6, d = i & 63;
            float v = g_K[(size_t)(b * SS + kt * CH + kr) * KW + kvh * HD + d];
            unsigned int hi = tf32_of(v);
            sKh[kr * PAD + d] = __uint_as_float(hi);
            sKl[kr * PAD + d] = __uint_as_float(tf32_of(v - __uint_as_float(hi)));
        }
        __syncthreads();

        float acc[4] = {0.f, 0.f, 0.f, 0.f};
        const int nloc = nc * 8 + g;
#pragma unroll
        for (int kk = 0; kk < 8; kk++) {
            const int c0 = kk * 8 + tg;
            unsigned int ah[4], al[4], bh_[2], bl_[2];
            ah[0] = __float_as_uint(sQh[(mq + g) * PAD + c0]);
            ah[1] = __float_as_uint(sQh[(mq + g + 8) * PAD + c0]);
            ah[2] = __float_as_uint(sQh[(mq + g) * PAD + c0 + 4]);
            ah[3] = __float_as_uint(sQh[(mq + g + 8) * PAD + c0 + 4]);
            al[0] = __float_as_uint(sQl[(mq + g) * PAD + c0]);
            al[1] = __float_as_uint(sQl[(mq + g + 8) * PAD + c0]);
            al[2] = __float_as_uint(sQl[(mq + g) * PAD + c0 + 4]);
            al[3] = __float_as_uint(sQl[(mq + g + 8) * PAD + c0 + 4]);
            bh_[0] = __float_as_uint(sKh[nloc * PAD + c0]);
            bh_[1] = __float_as_uint(sKh[nloc * PAD + c0 + 4]);
            bl_[0] = __float_as_uint(sKl[nloc * PAD + c0]);
            bl_[1] = __float_as_uint(sKl[nloc * PAD + c0 + 4]);
            mma_tf32u(acc, al, bh_);
            mma_tf32u(acc, ah, bl_);
            mma_tf32u(acc, ah, bh_);
        }
        const int col = kt * CH + nc * 8 + 2 * tg;
        const int r0q = q0 + mq + g, r1q = q0 + mq + g + 8;
        float v00 = acc[0] * scaling + ((col     > r0q) ? -1e9f : 0.f);
        float v01 = acc[1] * scaling + ((col + 1 > r0q) ? -1e9f : 0.f);
        float v10 = acc[2] * scaling + ((col     > r1q) ? -1e9f : 0.f);
        float v11 = acc[3] * scaling + ((col + 1 > r1q) ? -1e9f : 0.f);
        *(float2*)(sS + (mq + g) * SSP + col)     = make_float2(v00, v01);
        *(float2*)(sS + (mq + g + 8) * SSP + col) = make_float2(v10, v11);
    }
    __syncthreads();

    {
        for (int rw = 0; rw < 2; rw++) {
            int r = w * 2 + rw;
            float* row = sS + r * SSP;
            float m = -INFINITY;
            for (int cc = lane; cc < klim; cc += 32) m = fmaxf(m, row[cc]);
#pragma unroll
            for (int o = 16; o; o >>= 1) m = fmaxf(m, __shfl_xor_sync(0xffffffffu, m, o));
            float ssum = 0.f;
            for (int cc = lane; cc < klim; cc += 32) {
                float p = __expf(row[cc] - m);
                row[cc] = p;
                ssum += p;
            }
#pragma unroll
            for (int o = 16; o; o >>= 1) ssum += __shfl_xor_sync(0xffffffffu, ssum, o);
            float inv = 1.f / ssum;
            float* awrow = aw + ((size_t)(bh * SS + q0 + r)) * SS;
            for (int cc = lane; cc < klim; cc += 32) {
                float p = row[cc] * inv;
                row[cc] = p;
                awrow[cc] = p;
            }
            for (int cc = klim + lane; cc < SS; cc += 32) awrow[cc] = 0.f;
        }
    }

    float oacc[4] = {0.f, 0.f, 0.f, 0.f};
    for (int vt = 0; vt < nch; vt++) {
        __syncthreads();
        for (int i = tid; i < CH * HD; i += 512) {
            int vr = i >> 6, d = i & 63;
            float v = g_V[(size_t)(b * SS + vt * CH + vr) * KW + kvh * HD + d];
            unsigned int hi = tf32_of(v);
            sKh[vr * PAD + d] = __uint_as_float(hi);
            sKl[vr * PAD + d] = __uint_as_float(tf32_of(v - __uint_as_float(hi)));
        }
        __syncthreads();

#pragma unroll
        for (int kk = 0; kk < 8; kk++) {
            const int kc = vt * CH + kk * 8 + tg;
            float p0 = sS[(mq + g) * SSP + kc];
            float p1 = sS[(mq + g + 8) * SSP + kc];
            float p2 = sS[(mq + g) * SSP + kc + 4];
            float p3 = sS[(mq + g + 8) * SSP + kc + 4];
            unsigned int ah[4], al[4], bh_[2], bl_[2];
            ah[0] = tf32_of(p0); ah[1] = tf32_of(p1);
            ah[2] = tf32_of(p2); ah[3] = tf32_of(p3);
            al[0] = tf32_of(p0 - __uint_as_float(ah[0]));
            al[1] = tf32_of(p1 - __uint_as_float(ah[1]));
            al[2] = tf32_of(p2 - __uint_as_float(ah[2]));
            al[3] = tf32_of(p3 - __uint_as_float(ah[3]));
            const int krow = kk * 8 + tg;
            bh_[0] = __float_as_uint(sKh[krow * PAD + nc * 8 + g]);
            bh_[1] = __float_as_uint(sKh[(krow + 4) * PAD + nc * 8 + g]);
            bl_[0] = __float_as_uint(sKl[krow * PAD + nc * 8 + g]);
            bl_[1] = __float_as_uint(sKl[(krow + 4) * PAD + nc * 8 + g]);
            mma_tf32u(oacc, al, bh_);
            mma_tf32u(oacc, ah, bl_);
            mma_tf32u(oacc, ah, bh_);
        }
    }

    // write AO as bf16 hi/lo (feeds O-proj bf16 GEMM)
    {
        int r0 = b * SS + q0 + mq + g;
        int r1 = r0 + 8;
        int col = h * HD + nc * 8 + 2 * tg;
#pragma unroll
        for (int i = 0; i < 4; i++) {
            int rr = (i >> 1) ? r1 : r0;
            int cc = col + (i & 1);
            float v = oacc[i];
            __nv_bfloat16 hb = __float2bfloat16(v);
            g_AOh[(size_t)rr * QW + cc] = hb;
            g_AOl[(size_t)rr * QW + cc] = __float2bfloat16(v - __bfloat162float(hb));
        }
    }
}

// ---------------------------------------------------------------------------
// Launch
// ---------------------------------------------------------------------------
extern "C" void kernel_launch(void* const* d_in, const int* in_sizes, int n_in,
                              void* d_out, int out_size)
{
    const float* x    = (const float*)d_in[0];
    const float* cs   = (const float*)d_in[1];
    const float* sn   = (const float*)d_in[2];
    // d_in[3] = attention_mask (pure causal; reproduced analytically)
    const float* Wq   = (const float*)d_in[4];
    const float* Wk   = (const float*)d_in[5];
    const float* Wv   = (const float*)d_in[6];
    const float* Wo   = (const float*)d_in[7];

    float* out = (float*)d_out;
    float* aw  = out + (size_t)NROWS * HH;

    float *Qp, *Kp, *Vp;
    __nv_bfloat16 *xh, *xl, *Wqh, *Wql, *Wkh, *Wkl, *Wvh, *Wvl, *Woh, *Wol, *AOh, *AOl;
    cudaGetSymbolAddress((void**)&Qp,  g_Q);
    cudaGetSymbolAddress((void**)&Kp,  g_K);
    cudaGetSymbolAddress((void**)&Vp,  g_V);
    cudaGetSymbolAddress((void**)&xh,  g_xh);
    cudaGetSymbolAddress((void**)&xl,  g_xl);
    cudaGetSymbolAddress((void**)&Wqh, g_Wqh);
    cudaGetSymbolAddress((void**)&Wql, g_Wql);
    cudaGetSymbolAddress((void**)&Wkh, g_Wkh);
    cudaGetSymbolAddress((void**)&Wkl, g_Wkl);
    cudaGetSymbolAddress((void**)&Wvh, g_Wvh);
    cudaGetSymbolAddress((void**)&Wvl, g_Wvl);
    cudaGetSymbolAddress((void**)&Woh, g_Woh);
    cudaGetSymbolAddress((void**)&Wol, g_Wol);
    cudaGetSymbolAddress((void**)&AOh, g_AOh);
    cudaGetSymbolAddress((void**)&AOl, g_AOl);

    cudaFuncSetAttribute(attn_kernel, cudaFuncAttributeMaxDynamicSharedMemorySize, ATTN_SMEM);
    cudaFuncSetAttribute(gemm_bf16_3, cudaFuncAttributeMaxDynamicSharedMemorySize, HGEMM_SMEM);

    // Split inputs to bf16 hi/lo
    {
        int n = NROWS * HH;
        split_kernel<<<(n + 255) / 256, 256>>>(x, xh, xl, n);
        dim3 blk(32, 8);
        splitT_kernel<<<dim3(QW / 32, HH / 32), blk>>>(Wq, Wqh, Wql, HH, QW);
        splitT_kernel<<<dim3(KW / 32, HH / 32), blk>>>(Wk, Wkh, Wkl, HH, KW);
        splitT_kernel<<<dim3(KW / 32, HH / 32), blk>>>(Wv, Wvh, Wvl, HH, KW);
        splitT_kernel<<<dim3(HH / 32, QW / 32), blk>>>(Wo, Woh, Wol, QW, HH);
    }

    // Projections (3xBF16 tensor cores)
    {
        dim3 g(QW / 128, NROWS / 128);
        gemm_bf16_3<<<g, 256, HGEMM_SMEM>>>(xh, xl, Wqh, Wql, Qp, NROWS, QW, HH);
    }
    {
        dim3 g(KW / 128, NROWS / 128);
        gemm_bf16_3<<<g, 256, HGEMM_SMEM>>>(xh, xl, Wkh, Wkl, Kp, NROWS, KW, HH);
        gemm_bf16_3<<<g, 256, HGEMM_SMEM>>>(xh, xl, Wvh, Wvl, Vp, NROWS, KW, HH);
    }

    // RoPE
    {
        int totq = NROWS * NH * 32;
        rope_kernel<<<(totq + 255) / 256, 256>>>(Qp, cs, sn, NH);
        int totk = NROWS * NKV * 32;
        rope_kernel<<<(totk + 255) / 256, 256>>>(Kp, cs, sn, NKV);
    }

    // Attention (+ aw output, AO bf16 split)
    {
        int grid = BB * NH * NQT;   // 4096
        attn_kernel<<<grid, 512, ATTN_SMEM>>>(aw);
    }

    // Output projection
    {
        dim3 g(HH / 128, NROWS / 128);
        gemm_bf16_3<<<g, 256, HGEMM_SMEM>>>(AOh, AOl, Woh, Wol, out, NROWS, HH, QW);
    }

    (void)in_sizes; (void)n_in; (void)out_size;
}

// round 12
// speedup vs baseline: 2.9019x; 1.0809x over previous
#include <cuda_runtime.h>
#include <cuda_bf16.h>
#include <cstdint>
#include <math.h>

// Problem constants
#define BB 4
#define SS 1024
#define HH 2048
#define NH 32
#define NKV 8
#define HD 64
#define NROWS (BB*SS)          // 4096
#define QW (NH*HD)             // 2048
#define KW (NKV*HD)            // 512

// Scratch (device globals; no allocation allowed)
__device__ float g_Q[NROWS * QW];
__device__ float g_K[NROWS * KW];
__device__ float g_V[NROWS * KW];
__device__ __nv_bfloat16 g_xh[NROWS * HH],  g_xl[NROWS * HH];
__device__ __nv_bfloat16 g_Wqh[QW * HH],    g_Wql[QW * HH];     // [N][K]
__device__ __nv_bfloat16 g_Wkh[KW * HH],    g_Wkl[KW * HH];     // [N][K]
__device__ __nv_bfloat16 g_Wvh[KW * HH],    g_Wvl[KW * HH];     // [N][K]
__device__ __nv_bfloat16 g_Woh[HH * QW],    g_Wol[HH * QW];     // [N][K]
__device__ __nv_bfloat16 g_AOh[NROWS * QW], g_AOl[NROWS * QW];
__device__ __nv_bfloat16 g_Qh[NROWS * QW],  g_Ql[NROWS * QW];
__device__ __nv_bfloat16 g_Kh[NROWS * KW],  g_Kl[NROWS * KW];
__device__ __nv_bfloat16 g_Vh[NROWS * KW],  g_Vl[NROWS * KW];

// ---------------------------------------------------------------------------
// helpers
// ---------------------------------------------------------------------------
__device__ __forceinline__ void cp16(unsigned int dst, const void* src) {
    asm volatile("cp.async.cg.shared.global [%0], [%1], 16;\n" :: "r"(dst), "l"(src));
}

__device__ __forceinline__ void mma_bf16(float* c, const unsigned int* a,
                                         const unsigned int* b) {
    asm volatile(
        "mma.sync.aligned.m16n8k16.row.col.f32.bf16.bf16.f32 "
        "{%0,%1,%2,%3}, {%4,%5,%6,%7}, {%8,%9}, {%0,%1,%2,%3};\n"
        : "+f"(c[0]), "+f"(c[1]), "+f"(c[2]), "+f"(c[3])
        : "r"(a[0]), "r"(a[1]), "r"(a[2]), "r"(a[3]),
          "r"(b[0]), "r"(b[1]));
}

__device__ __forceinline__ unsigned int packbf(__nv_bfloat16 a, __nv_bfloat16 b) {
    __nv_bfloat162 t;
    t.x = a; t.y = b;
    return *(unsigned int*)&t;
}

// ---------------------------------------------------------------------------
// Split kernels: fp32 -> bf16 hi/lo (plain + transposing)
// ---------------------------------------------------------------------------
__global__ void split_kernel(const float* __restrict__ src,
                             __nv_bfloat16* __restrict__ h,
                             __nv_bfloat16* __restrict__ l, int n)
{
    int i = blockIdx.x * blockDim.x + threadIdx.x;
    if (i >= n) return;
    float v = src[i];
    __nv_bfloat16 hb = __float2bfloat16(v);
    h[i] = hb;
    l[i] = __float2bfloat16(v - __bfloat162float(hb));
}

// src [K][N] fp32 -> dst [N][K] bf16 hi/lo
__global__ void splitT_kernel(const float* __restrict__ src,
                              __nv_bfloat16* __restrict__ h,
                              __nv_bfloat16* __restrict__ l, int K, int N)
{
    __shared__ float t[32][33];
    int k0 = blockIdx.y * 32, n0 = blockIdx.x * 32;
    int tx = threadIdx.x, ty = threadIdx.y;   // 32x8
#pragma unroll
    for (int i = 0; i < 32; i += 8)
        t[ty + i][tx] = src[(size_t)(k0 + ty + i) * N + n0 + tx];
    __syncthreads();
#pragma unroll
    for (int i = 0; i < 32; i += 8) {
        float v = t[tx][ty + i];
        __nv_bfloat16 hb = __float2bfloat16(v);
        size_t o = (size_t)(n0 + ty + i) * K + k0 + tx;
        h[o] = hb;
        l[o] = __float2bfloat16(v - __bfloat162float(hb));
    }
}

// RoPE + split: read fp32 T (pre-rope), write rotated bf16 hi/lo
__global__ void rope_split_kernel(const float* __restrict__ T,
                                  const float* __restrict__ cs,
                                  const float* __restrict__ sn,
                                  int nheads,
                                  __nv_bfloat16* __restrict__ oh,
                                  __nv_bfloat16* __restrict__ ol)
{
    int idx = blockIdx.x * blockDim.x + threadIdx.x;
    int total = NROWS * nheads * 32;
    if (idx >= total) return;
    int p   = idx & 31;
    int hh  = (idx >> 5) % nheads;
    int row = idx / (32 * nheads);

    float c1 = cs[row * HD + p];
    float c2 = cs[row * HD + p + 32];
    float s1 = sn[row * HD + p];
    float s2 = sn[row * HD + p + 32];

    const float* base = T + (size_t)row * (nheads * HD) + hh * HD;
    float x1 = base[p];
    float x2 = base[p + 32];
    float v1 = x1 * c1 - x2 * s1;
    float v2 = x2 * c2 + x1 * s2;

    size_t o = (size_t)row * (nheads * HD) + hh * HD;
    __nv_bfloat16 h1 = __float2bfloat16(v1);
    __nv_bfloat16 h2 = __float2bfloat16(v2);
    oh[o + p]      = h1;
    ol[o + p]      = __float2bfloat16(v1 - __bfloat162float(h1));
    oh[o + p + 32] = h2;
    ol[o + p + 32] = __float2bfloat16(v2 - __bfloat162float(h2));
}

// ---------------------------------------------------------------------------
// 3xBF16 tensor-core GEMM: C[M,N] = A[M,K] @ B[N,K]^T (unchanged from R10)
// ---------------------------------------------------------------------------
#define HST 40
#define HTILE (128*HST)
#define HGEMM_SMEM (2*4*HTILE*2)   // 81920 B

__global__ __launch_bounds__(256) void gemm_bf16_3(
    const __nv_bfloat16* __restrict__ Ah, const __nv_bfloat16* __restrict__ Al,
    const __nv_bfloat16* __restrict__ Bh, const __nv_bfloat16* __restrict__ Bl,
    float* __restrict__ C, int M, int N, int K)
{
    extern __shared__ __nv_bfloat16 hsm[];
    const int tid = threadIdx.x;
    const int wid = tid >> 5, lane = tid & 31;
    const int g = lane >> 2, tg = lane & 3;
    const int warp_m = wid & 3;
    const int warp_n = wid >> 2;
    const int bx = blockIdx.x, by = blockIdx.y;

    unsigned int sbase = (unsigned int)__cvta_generic_to_shared(hsm);

    float acc[2][8][4];
#pragma unroll
    for (int i = 0; i < 2; i++)
#pragma unroll
        for (int j = 0; j < 8; j++)
#pragma unroll
            for (int q = 0; q < 4; q++) acc[i][j][q] = 0.f;

    const int KT = K / 32;

    auto load_tile = [&](int buf, int k0) {
        unsigned int b0 = sbase + buf * (4 * HTILE * 2);
#pragma unroll
        for (int i = 0; i < 2; i++) {
            int c = i * 256 + tid;
            int row = c >> 2, ch = c & 3;
            unsigned int soff = (row * HST + ch * 8) * 2;
            size_t aoff = (size_t)(by * 128 + row) * K + k0 + ch * 8;
            size_t boff = (size_t)(bx * 128 + row) * K + k0 + ch * 8;
            cp16(b0 + soff,                 Ah + aoff);
            cp16(b0 + HTILE * 2 + soff,     Al + aoff);
            cp16(b0 + 2 * HTILE * 2 + soff, Bh + boff);
            cp16(b0 + 3 * HTILE * 2 + soff, Bl + boff);
        }
        asm volatile("cp.async.commit_group;\n");
    };

    load_tile(0, 0);

    for (int kt = 0; kt < KT; kt++) {
        const int cur = kt & 1;
        if (kt + 1 < KT) {
            load_tile(cur ^ 1, (kt + 1) * 32);
            asm volatile("cp.async.wait_group 1;\n");
        } else {
            asm volatile("cp.async.wait_group 0;\n");
        }
        __syncthreads();

        const __nv_bfloat16* sAh = hsm + cur * 4 * HTILE;
        const __nv_bfloat16* sAl = sAh + HTILE;
        const __nv_bfloat16* sBh = sAl + HTILE;
        const __nv_bfloat16* sBl = sBh + HTILE;
        const int m0 = warp_m * 32;
        const int n0 = warp_n * 64;

#pragma unroll
        for (int kk = 0; kk < 2; kk++) {
            unsigned int ah[2][4], al_[2][4];
#pragma unroll
            for (int mf = 0; mf < 2; mf++) {
                int base = (m0 + mf * 16 + g) * HST + kk * 16 + 2 * tg;
                ah[mf][0] = *(const unsigned int*)&sAh[base];
                ah[mf][1] = *(const unsigned int*)&sAh[base + 8 * HST];
                ah[mf][2] = *(const unsigned int*)&sAh[base + 8];
                ah[mf][3] = *(const unsigned int*)&sAh[base + 8 * HST + 8];
                al_[mf][0] = *(const unsigned int*)&sAl[base];
                al_[mf][1] = *(const unsigned int*)&sAl[base + 8 * HST];
                al_[mf][2] = *(const unsigned int*)&sAl[base + 8];
                al_[mf][3] = *(const unsigned int*)&sAl[base + 8 * HST + 8];
            }
#pragma unroll
            for (int nf = 0; nf < 8; nf++) {
                int bb = (n0 + nf * 8 + g) * HST + kk * 16 + 2 * tg;
                unsigned int bh2[2], bl2[2];
                bh2[0] = *(const unsigned int*)&sBh[bb];
                bh2[1] = *(const unsigned int*)&sBh[bb + 8];
                bl2[0] = *(const unsigned int*)&sBl[bb];
                bl2[1] = *(const unsigned int*)&sBl[bb + 8];
#pragma unroll
                for (int mf = 0; mf < 2; mf++) {
                    mma_bf16(acc[mf][nf], ah[mf], bl2);
                    mma_bf16(acc[mf][nf], al_[mf], bh2);
                    mma_bf16(acc[mf][nf], ah[mf], bh2);
                }
            }
        }
        __syncthreads();
    }

#pragma unroll
    for (int mf = 0; mf < 2; mf++) {
#pragma unroll
        for (int nf = 0; nf < 8; nf++) {
            int row = by * 128 + warp_m * 32 + mf * 16 + g;
            int col = bx * 128 + warp_n * 64 + nf * 8 + 2 * tg;
            float* cp = C + (size_t)row * N + col;
            *(float2*)cp           = make_float2(acc[mf][nf][0], acc[mf][nf][1]);
            *(float2*)(cp + 8 * N) = make_float2(acc[mf][nf][2], acc[mf][nf][3]);
        }
    }
}

// ---------------------------------------------------------------------------
// BF16 tensor-core attention: block = (b,h,32 q rows), 512 threads / 16 warps.
// QK/PV via 3xBF16 m16n8k16; Q/K pre-split in global (cp.async in),
// V pre-split + transposed into smem. Causal chunk skip.
// ---------------------------------------------------------------------------
#define QT 32
#define CH 64
#define QST 72          // Q/K smem row stride (bf16): 64 data + 8 pad
#define VST 72          // V^T smem row stride (bf16)
#define SSP 1028
#define NQT (SS/QT)     // 32
// bytes: sQh+sQl = 2*32*72*2 = 9216; sK/V region 2*4608*2 = 18432; sS 131584
#define ATTN_SMEM (9216 + 18432 + QT*SSP*4)   // 159232

__global__ __launch_bounds__(512) void attn_kernel(float* __restrict__ aw)
{
    extern __shared__ char smc[];
    __nv_bfloat16* sQh = (__nv_bfloat16*)smc;          // 32*72
    __nv_bfloat16* sQl = sQh + QT * QST;
    __nv_bfloat16* sKh = sQl + QT * QST;               // 4608 elems (K or V^T)
    __nv_bfloat16* sKl = sKh + 4608;
    float* sS = (float*)(sKl + 4608);                  // 32*1028

    const int qt = blockIdx.x & (NQT - 1);
    const int bh = blockIdx.x / NQT;
    const int b  = bh / NH;
    const int h  = bh % NH;
    const int kvh = h / (NH / NKV);
    const int tid = threadIdx.x;
    const int w = tid >> 5, lane = tid & 31;
    const int g = lane >> 2, tg = lane & 3;
    const int mq = (w >> 3) * 16;
    const int nc = w & 7;
    const int q0 = qt * QT;
    const float scaling = 0.125f;

    const int nch  = (q0 + QT + CH - 1) / CH;
    const int klim = nch * CH;

    // --- Q tile via cp.async (pre-split bf16) ---
    {
        int halfsel = tid >> 8;              // 0=h, 1=l
        int idx = tid & 255;
        int r = idx >> 3, ch = idx & 7;
        const __nv_bfloat16* src = (halfsel ? g_Ql : g_Qh)
            + (size_t)(b * SS + q0 + r) * QW + h * HD + ch * 8;
        __nv_bfloat16* dst = (halfsel ? sQl : sQh) + r * QST + ch * 8;
        cp16((unsigned int)__cvta_generic_to_shared(dst), src);
        asm volatile("cp.async.commit_group;\n");
    }

    // --- QK^T over nch chunks ---
    for (int kt = 0; kt < nch; kt++) {
        __syncthreads();
#pragma unroll
        for (int i = 0; i < 2; i++) {
            int c = i * 512 + tid;
            int halfsel = c >> 9;
            int rem = c & 511;
            int kr = rem >> 3, ch = rem & 7;
            const __nv_bfloat16* src = (halfsel ? g_Kl : g_Kh)
                + (size_t)(b * SS + kt * CH + kr) * KW + kvh * HD + ch * 8;
            __nv_bfloat16* dst = (halfsel ? sKl : sKh) + kr * QST + ch * 8;
            cp16((unsigned int)__cvta_generic_to_shared(dst), src);
        }
        asm volatile("cp.async.commit_group;\n");
        asm volatile("cp.async.wait_group 0;\n");
        __syncthreads();

        float acc[4] = {0.f, 0.f, 0.f, 0.f};
#pragma unroll
        for (int kk = 0; kk < 4; kk++) {
            int abase = (mq + g) * QST + kk * 16 + 2 * tg;
            unsigned int ah[4], al[4];
            ah[0] = *(const unsigned int*)&sQh[abase];
            ah[1] = *(const unsigned int*)&sQh[abase + 8 * QST];
            ah[2] = *(const unsigned int*)&sQh[abase + 8];
            ah[3] = *(const unsigned int*)&sQh[abase + 8 * QST + 8];
            al[0] = *(const unsigned int*)&sQl[abase];
            al[1] = *(const unsigned int*)&sQl[abase + 8 * QST];
            al[2] = *(const unsigned int*)&sQl[abase + 8];
            al[3] = *(const unsigned int*)&sQl[abase + 8 * QST + 8];
            int bb = (nc * 8 + g) * QST + kk * 16 + 2 * tg;
            unsigned int bh2[2], bl2[2];
            bh2[0] = *(const unsigned int*)&sKh[bb];
            bh2[1] = *(const unsigned int*)&sKh[bb + 8];
            bl2[0] = *(const unsigned int*)&sKl[bb];
            bl2[1] = *(const unsigned int*)&sKl[bb + 8];
            mma_bf16(acc, ah, bl2);
            mma_bf16(acc, al, bh2);
            mma_bf16(acc, ah, bh2);
        }
        const int col = kt * CH + nc * 8 + 2 * tg;
        const int r0q = q0 + mq + g, r1q = q0 + mq + g + 8;
        float v00 = acc[0] * scaling + ((col     > r0q) ? -1e9f : 0.f);
        float v01 = acc[1] * scaling + ((col + 1 > r0q) ? -1e9f : 0.f);
        float v10 = acc[2] * scaling + ((col     > r1q) ? -1e9f : 0.f);
        float v11 = acc[3] * scaling + ((col + 1 > r1q) ? -1e9f : 0.f);
        *(float2*)(sS + (mq + g) * SSP + col)     = make_float2(v00, v01);
        *(float2*)(sS + (mq + g + 8) * SSP + col) = make_float2(v10, v11);
    }
    __syncthreads();

    // --- softmax (16 warps x 2 rows), cols < klim; aw zero-fill beyond ---
    {
        for (int rw = 0; rw < 2; rw++) {
            int r = w * 2 + rw;
            float* row = sS + r * SSP;
            float m = -INFINITY;
            for (int cc = lane; cc < klim; cc += 32) m = fmaxf(m, row[cc]);
#pragma unroll
            for (int o = 16; o; o >>= 1) m = fmaxf(m, __shfl_xor_sync(0xffffffffu, m, o));
            float ssum = 0.f;
            for (int cc = lane; cc < klim; cc += 32) {
                float p = __expf(row[cc] - m);
                row[cc] = p;
                ssum += p;
            }
#pragma unroll
            for (int o = 16; o; o >>= 1) ssum += __shfl_xor_sync(0xffffffffu, ssum, o);
            float inv = 1.f / ssum;
            float* awrow = aw + ((size_t)(bh * SS + q0 + r)) * SS;
            for (int cc = lane; cc < klim; cc += 32) {
                float p = row[cc] * inv;
                row[cc] = p;
                awrow[cc] = p;
            }
            for (int cc = klim + lane; cc < SS; cc += 32) awrow[cc] = 0.f;
        }
    }

    // --- PV over nch chunks (V^T in smem) ---
    float oacc[4] = {0.f, 0.f, 0.f, 0.f};
    for (int vt = 0; vt < nch; vt++) {
        __syncthreads();
        // load V chunk transposed: sVt[d][key], stride VST
        for (int i = tid; i < CH * 32; i += 512) {    // 2048 u32 per half
            int key = i >> 5, d2 = i & 31;
            size_t go = (size_t)(b * SS + vt * CH + key) * KW + kvh * HD + d2 * 2;
            __nv_bfloat162 vh = *(const __nv_bfloat162*)(g_Vh + go);
            __nv_bfloat162 vl = *(const __nv_bfloat162*)(g_Vl + go);
            sKh[(2 * d2) * VST + key]     = vh.x;
            sKh[(2 * d2 + 1) * VST + key] = vh.y;
            sKl[(2 * d2) * VST + key]     = vl.x;
            sKl[(2 * d2 + 1) * VST + key] = vl.y;
        }
        __syncthreads();

#pragma unroll
        for (int kk = 0; kk < 4; kk++) {
            const int col0 = vt * CH + kk * 16 + 2 * tg;
            float2 q00 = *(const float2*)(sS + (mq + g) * SSP + col0);
            float2 q01 = *(const float2*)(sS + (mq + g) * SSP + col0 + 8);
            float2 q10 = *(const float2*)(sS + (mq + g + 8) * SSP + col0);
            float2 q11 = *(const float2*)(sS + (mq + g + 8) * SSP + col0 + 8);

            __nv_bfloat16 h00x = __float2bfloat16(q00.x), h00y = __float2bfloat16(q00.y);
            __nv_bfloat16 h01x = __float2bfloat16(q01.x), h01y = __float2bfloat16(q01.y);
            __nv_bfloat16 h10x = __float2bfloat16(q10.x), h10y = __float2bfloat16(q10.y);
            __nv_bfloat16 h11x = __float2bfloat16(q11.x), h11y = __float2bfloat16(q11.y);

            unsigned int ah[4], al[4];
            ah[0] = packbf(h00x, h00y);
            ah[1] = packbf(h10x, h10y);
            ah[2] = packbf(h01x, h01y);
            ah[3] = packbf(h11x, h11y);
            al[0] = packbf(__float2bfloat16(q00.x - __bfloat162float(h00x)),
                           __float2bfloat16(q00.y - __bfloat162float(h00y)));
            al[1] = packbf(__float2bfloat16(q10.x - __bfloat162float(h10x)),
                           __float2bfloat16(q10.y - __bfloat162float(h10y)));
            al[2] = packbf(__float2bfloat16(q01.x - __bfloat162float(h01x)),
                           __float2bfloat16(q01.y - __bfloat162float(h01y)));
            al[3] = packbf(__float2bfloat16(q11.x - __bfloat162float(h11x)),
                           __float2bfloat16(q11.y - __bfloat162float(h11y)));

            int bb = (nc * 8 + g) * VST + kk * 16 + 2 * tg;
            unsigned int bh2[2], bl2[2];
            bh2[0] = *(const unsigned int*)&sKh[bb];
            bh2[1] = *(const unsigned int*)&sKh[bb + 8];
            bl2[0] = *(const unsigned int*)&sKl[bb];
            bl2[1] = *(const unsigned int*)&sKl[bb + 8];
            mma_bf16(oacc, ah, bl2);
            mma_bf16(oacc, al, bh2);
            mma_bf16(oacc, ah, bh2);
        }
    }

    // write AO as bf16 hi/lo (feeds O-proj bf16 GEMM)
    {
        int r0 = b * SS + q0 + mq + g;
        int r1 = r0 + 8;
        int col = h * HD + nc * 8 + 2 * tg;
#pragma unroll
        for (int i = 0; i < 4; i++) {
            int rr = (i >> 1) ? r1 : r0;
            int cc = col + (i & 1);
            float v = oacc[i];
            __nv_bfloat16 hb = __float2bfloat16(v);
            g_AOh[(size_t)rr * QW + cc] = hb;
            g_AOl[(size_t)rr * QW + cc] = __float2bfloat16(v - __bfloat162float(hb));
        }
    }
}

// ---------------------------------------------------------------------------
// Launch
// ---------------------------------------------------------------------------
extern "C" void kernel_launch(void* const* d_in, const int* in_sizes, int n_in,
                              void* d_out, int out_size)
{
    const float* x    = (const float*)d_in[0];
    const float* cs   = (const float*)d_in[1];
    const float* sn   = (const float*)d_in[2];
    // d_in[3] = attention_mask (pure causal; reproduced analytically)
    const float* Wq   = (const float*)d_in[4];
    const float* Wk   = (const float*)d_in[5];
    const float* Wv   = (const float*)d_in[6];
    const float* Wo   = (const float*)d_in[7];

    float* out = (float*)d_out;
    float* aw  = out + (size_t)NROWS * HH;

    float *Qp, *Kp, *Vp;
    __nv_bfloat16 *xh, *xl, *Wqh, *Wql, *Wkh, *Wkl, *Wvh, *Wvl, *Woh, *Wol, *AOh, *AOl;
    __nv_bfloat16 *Qh, *Ql, *Kh, *Kl, *Vh, *Vl;
    cudaGetSymbolAddress((void**)&Qp,  g_Q);
    cudaGetSymbolAddress((void**)&Kp,  g_K);
    cudaGetSymbolAddress((void**)&Vp,  g_V);
    cudaGetSymbolAddress((void**)&xh,  g_xh);
    cudaGetSymbolAddress((void**)&xl,  g_xl);
    cudaGetSymbolAddress((void**)&Wqh, g_Wqh);
    cudaGetSymbolAddress((void**)&Wql, g_Wql);
    cudaGetSymbolAddress((void**)&Wkh, g_Wkh);
    cudaGetSymbolAddress((void**)&Wkl, g_Wkl);
    cudaGetSymbolAddress((void**)&Wvh, g_Wvh);
    cudaGetSymbolAddress((void**)&Wvl, g_Wvl);
    cudaGetSymbolAddress((void**)&Woh, g_Woh);
    cudaGetSymbolAddress((void**)&Wol, g_Wol);
    cudaGetSymbolAddress((void**)&AOh, g_AOh);
    cudaGetSymbolAddress((void**)&AOl, g_AOl);
    cudaGetSymbolAddress((void**)&Qh,  g_Qh);
    cudaGetSymbolAddress((void**)&Ql,  g_Ql);
    cudaGetSymbolAddress((void**)&Kh,  g_Kh);
    cudaGetSymbolAddress((void**)&Kl,  g_Kl);
    cudaGetSymbolAddress((void**)&Vh,  g_Vh);
    cudaGetSymbolAddress((void**)&Vl,  g_Vl);

    cudaFuncSetAttribute(attn_kernel, cudaFuncAttributeMaxDynamicSharedMemorySize, ATTN_SMEM);
    cudaFuncSetAttribute(gemm_bf16_3, cudaFuncAttributeMaxDynamicSharedMemorySize, HGEMM_SMEM);

    // Split inputs to bf16 hi/lo
    {
        int n = NROWS * HH;
        split_kernel<<<(n + 255) / 256, 256>>>(x, xh, xl, n);
        dim3 blk(32, 8);
        splitT_kernel<<<dim3(QW / 32, HH / 32), blk>>>(Wq, Wqh, Wql, HH, QW);
        splitT_kernel<<<dim3(KW / 32, HH / 32), blk>>>(Wk, Wkh, Wkl, HH, KW);
        splitT_kernel<<<dim3(KW / 32, HH / 32), blk>>>(Wv, Wvh, Wvl, HH, KW);
        splitT_kernel<<<dim3(HH / 32, QW / 32), blk>>>(Wo, Woh, Wol, QW, HH);
    }

    // Projections (3xBF16 tensor cores)
    {
        dim3 g(QW / 128, NROWS / 128);
        gemm_bf16_3<<<g, 256, HGEMM_SMEM>>>(xh, xl, Wqh, Wql, Qp, NROWS, QW, HH);
    }
    {
        dim3 g(KW / 128, NROWS / 128);
        gemm_bf16_3<<<g, 256, HGEMM_SMEM>>>(xh, xl, Wkh, Wkl, Kp, NROWS, KW, HH);
        gemm_bf16_3<<<g, 256, HGEMM_SMEM>>>(xh, xl, Wvh, Wvl, Vp, NROWS, KW, HH);
    }

    // RoPE + split Q/K; split V
    {
        int totq = NROWS * NH * 32;
        rope_split_kernel<<<(totq + 255) / 256, 256>>>(Qp, cs, sn, NH, Qh, Ql);
        int totk = NROWS * NKV * 32;
        rope_split_kernel<<<(totk + 255) / 256, 256>>>(Kp, cs, sn, NKV, Kh, Kl);
        int nv = NROWS * KW;
        split_kernel<<<(nv + 255) / 256, 256>>>(Vp, Vh, Vl, nv);
    }

    // Attention (+ aw output, AO bf16 split)
    {
        int grid = BB * NH * NQT;   // 4096
        attn_kernel<<<grid, 512, ATTN_SMEM>>>(aw);
    }

    // Output projection
    {
        dim3 g(HH / 128, NROWS / 128);
        gemm_bf16_3<<<g, 256, HGEMM_SMEM>>>(AOh, AOl, Woh, Wol, out, NROWS, HH, QW);
    }

    (void)in_sizes; (void)n_in; (void)out_size;
}

// round 13
// speedup vs baseline: 3.0702x; 1.0580x over previous
#include <cuda_runtime.h>
#include <cuda_bf16.h>
#include <cstdint>
#include <math.h>

// Problem constants
#define BB 4
#define SS 1024
#define HH 2048
#define NH 32
#define NKV 8
#define HD 64
#define NROWS (BB*SS)          // 4096
#define QW (NH*HD)             // 2048
#define KW (NKV*HD)            // 512
#define NALL (QW + 2*KW)       // 3072

// Scratch (device globals; no allocation allowed)
__device__ float g_Q[NROWS * QW];
__device__ float g_K[NROWS * KW];
__device__ float g_V[NROWS * KW];
__device__ __nv_bfloat16 g_xh[NROWS * HH],   g_xl[NROWS * HH];
__device__ __nv_bfloat16 g_Wallh[NALL * HH], g_Walll[NALL * HH]; // [3072][2048]
__device__ __nv_bfloat16 g_Woh[HH * QW],     g_Wol[HH * QW];     // [N][K]
__device__ __nv_bfloat16 g_AOh[NROWS * QW],  g_AOl[NROWS * QW];
__device__ __nv_bfloat16 g_Qh[NROWS * QW],   g_Ql[NROWS * QW];
__device__ __nv_bfloat16 g_Kh[NROWS * KW],   g_Kl[NROWS * KW];
__device__ __nv_bfloat16 g_Vh[NROWS * KW],   g_Vl[NROWS * KW];

// ---------------------------------------------------------------------------
// helpers
// ---------------------------------------------------------------------------
__device__ __forceinline__ void cp16(unsigned int dst, const void* src) {
    asm volatile("cp.async.cg.shared.global [%0], [%1], 16;\n" :: "r"(dst), "l"(src));
}

__device__ __forceinline__ void mma_bf16(float* c, const unsigned int* a,
                                         const unsigned int* b) {
    asm volatile(
        "mma.sync.aligned.m16n8k16.row.col.f32.bf16.bf16.f32 "
        "{%0,%1,%2,%3}, {%4,%5,%6,%7}, {%8,%9}, {%0,%1,%2,%3};\n"
        : "+f"(c[0]), "+f"(c[1]), "+f"(c[2]), "+f"(c[3])
        : "r"(a[0]), "r"(a[1]), "r"(a[2]), "r"(a[3]),
          "r"(b[0]), "r"(b[1]));
}

__device__ __forceinline__ void ldsm4(unsigned int* r, unsigned int addr) {
    asm volatile("ldmatrix.sync.aligned.m8n8.x4.shared.b16 {%0,%1,%2,%3}, [%4];"
        : "=r"(r[0]), "=r"(r[1]), "=r"(r[2]), "=r"(r[3]) : "r"(addr));
}

__device__ __forceinline__ unsigned int packbf(__nv_bfloat16 a, __nv_bfloat16 b) {
    __nv_bfloat162 t;
    t.x = a; t.y = b;
    return *(unsigned int*)&t;
}

// ---------------------------------------------------------------------------
// Split kernels: fp32 -> bf16 hi/lo (plain + transposing)
// ---------------------------------------------------------------------------
__global__ void split_kernel(const float* __restrict__ src,
                             __nv_bfloat16* __restrict__ h,
                             __nv_bfloat16* __restrict__ l, int n)
{
    int i = blockIdx.x * blockDim.x + threadIdx.x;
    if (i >= n) return;
    float v = src[i];
    __nv_bfloat16 hb = __float2bfloat16(v);
    h[i] = hb;
    l[i] = __float2bfloat16(v - __bfloat162float(hb));
}

// src [K][N] fp32 -> dst [N][K] bf16 hi/lo
__global__ void splitT_kernel(const float* __restrict__ src,
                              __nv_bfloat16* __restrict__ h,
                              __nv_bfloat16* __restrict__ l, int K, int N)
{
    __shared__ float t[32][33];
    int k0 = blockIdx.y * 32, n0 = blockIdx.x * 32;
    int tx = threadIdx.x, ty = threadIdx.y;   // 32x8
#pragma unroll
    for (int i = 0; i < 32; i += 8)
        t[ty + i][tx] = src[(size_t)(k0 + ty + i) * N + n0 + tx];
    __syncthreads();
#pragma unroll
    for (int i = 0; i < 32; i += 8) {
        float v = t[tx][ty + i];
        __nv_bfloat16 hb = __float2bfloat16(v);
        size_t o = (size_t)(n0 + ty + i) * K + k0 + tx;
        h[o] = hb;
        l[o] = __float2bfloat16(v - __bfloat162float(hb));
    }
}

// RoPE + split: read fp32 T (pre-rope), write rotated bf16 hi/lo
__global__ void rope_split_kernel(const float* __restrict__ T,
                                  const float* __restrict__ cs,
                                  const float* __restrict__ sn,
                                  int nheads,
                                  __nv_bfloat16* __restrict__ oh,
                                  __nv_bfloat16* __restrict__ ol)
{
    int idx = blockIdx.x * blockDim.x + threadIdx.x;
    int total = NROWS * nheads * 32;
    if (idx >= total) return;
    int p   = idx & 31;
    int hh  = (idx >> 5) % nheads;
    int row = idx / (32 * nheads);

    float c1 = cs[row * HD + p];
    float c2 = cs[row * HD + p + 32];
    float s1 = sn[row * HD + p];
    float s2 = sn[row * HD + p + 32];

    const float* base = T + (size_t)row * (nheads * HD) + hh * HD;
    float x1 = base[p];
    float x2 = base[p + 32];
    float v1 = x1 * c1 - x2 * s1;
    float v2 = x2 * c2 + x1 * s2;

    size_t o = (size_t)row * (nheads * HD) + hh * HD;
    __nv_bfloat16 h1 = __float2bfloat16(v1);
    __nv_bfloat16 h2 = __float2bfloat16(v2);
    oh[o + p]      = h1;
    ol[o + p]      = __float2bfloat16(v1 - __bfloat162float(h1));
    oh[o + p + 32] = h2;
    ol[o + p + 32] = __float2bfloat16(v2 - __bfloat162float(h2));
}

// ---------------------------------------------------------------------------
// 3xBF16 GEMM with ldmatrix, K=2048 fixed, multi-output routing.
// C[M=4096, ...] = A[4096,2048] @ B[n,2048]^T.  bx<16 -> C0 (N=2048),
// bx<20 -> C1 (N=512), else C2 (N=512).  128x128x32 tiles, 256 thr.
// ---------------------------------------------------------------------------
#define HST 40               // smem row stride (bf16)
#define HTILE (128*HST)      // elems per half-tile
#define TBYTES (HTILE*2)     // 10240 bytes
#define HGEMM_SMEM (2*4*TBYTES)   // 81920 B
#define GK 2048
#define GKT (GK/32)

__global__ __launch_bounds__(256) void gemm3(
    const __nv_bfloat16* __restrict__ Ah, const __nv_bfloat16* __restrict__ Al,
    const __nv_bfloat16* __restrict__ Bh, const __nv_bfloat16* __restrict__ Bl,
    float* __restrict__ C0, float* __restrict__ C1, float* __restrict__ C2)
{
    extern __shared__ __nv_bfloat16 hsm[];
    const int tid = threadIdx.x;
    const int wid = tid >> 5, lane = tid & 31;
    const int g = lane >> 2, tg = lane & 3;
    const int warp_m = wid & 3;
    const int warp_n = wid >> 2;
    const int bx = blockIdx.x, by = blockIdx.y;

    unsigned int sbase = (unsigned int)__cvta_generic_to_shared(hsm);

    float acc[2][8][4];
#pragma unroll
    for (int i = 0; i < 2; i++)
#pragma unroll
        for (int j = 0; j < 8; j++)
#pragma unroll
            for (int q = 0; q < 4; q++) acc[i][j][q] = 0.f;

    auto load_tile = [&](int buf, int k0) {
        unsigned int b0 = sbase + buf * (4 * TBYTES);
#pragma unroll
        for (int i = 0; i < 2; i++) {
            int c = i * 256 + tid;
            int row = c >> 2, ch = c & 3;
            unsigned int soff = (row * HST + ch * 8) * 2;
            size_t aoff = (size_t)(by * 128 + row) * GK + k0 + ch * 8;
            size_t boff = (size_t)(bx * 128 + row) * GK + k0 + ch * 8;
            cp16(b0 + soff,              Ah + aoff);
            cp16(b0 + TBYTES + soff,     Al + aoff);
            cp16(b0 + 2 * TBYTES + soff, Bh + boff);
            cp16(b0 + 3 * TBYTES + soff, Bl + boff);
        }
        asm volatile("cp.async.commit_group;\n");
    };

    // per-thread ldmatrix element offsets (within a half-tile)
    const int m0 = warp_m * 32, n0 = warp_n * 64;
    const int a_off0 = (m0 + (lane & 15)) * HST + ((lane >> 4) << 3);
    const int a_off1 = a_off0 + 16 * HST;
    const int b_off  = (n0 + ((lane >> 4) & 1) * 8 + (lane & 7)) * HST
                     + ((lane >> 3) & 1) * 8;

    load_tile(0, 0);

    for (int kt = 0; kt < GKT; kt++) {
        const int cur = kt & 1;
        if (kt + 1 < GKT) {
            load_tile(cur ^ 1, (kt + 1) * 32);
            asm volatile("cp.async.wait_group 1;\n");
        } else {
            asm volatile("cp.async.wait_group 0;\n");
        }
        __syncthreads();

        unsigned int bufb = sbase + cur * (4 * TBYTES);
        unsigned int aH0 = bufb + a_off0 * 2;
        unsigned int aH1 = bufb + a_off1 * 2;
        unsigned int aL0 = aH0 + TBYTES;
        unsigned int aL1 = aH1 + TBYTES;
        unsigned int bH  = bufb + 2 * TBYTES + b_off * 2;
        unsigned int bL  = bH + TBYTES;

#pragma unroll
        for (int kk = 0; kk < 2; kk++) {
            const int ko = kk * 32;   // 16 elems = 32 bytes
            unsigned int ah[2][4], al_[2][4];
            ldsm4(ah[0],  aH0 + ko);
            ldsm4(ah[1],  aH1 + ko);
            ldsm4(al_[0], aL0 + ko);
            ldsm4(al_[1], aL1 + ko);
#pragma unroll
            for (int nfp = 0; nfp < 4; nfp++) {
                unsigned int bh4[4], bl4[4];
                const unsigned int bo = nfp * (16 * HST * 2) + ko;
                ldsm4(bh4, bH + bo);
                ldsm4(bl4, bL + bo);
#pragma unroll
                for (int mf = 0; mf < 2; mf++) {
                    mma_bf16(acc[mf][2 * nfp],     ah[mf],  bl4);
                    mma_bf16(acc[mf][2 * nfp],     al_[mf], bh4);
                    mma_bf16(acc[mf][2 * nfp],     ah[mf],  bh4);
                    mma_bf16(acc[mf][2 * nfp + 1], ah[mf],  bl4 + 2);
                    mma_bf16(acc[mf][2 * nfp + 1], al_[mf], bh4 + 2);
                    mma_bf16(acc[mf][2 * nfp + 1], ah[mf],  bh4 + 2);
                }
            }
        }
        __syncthreads();
    }

    // epilogue: route output by bx
    float* C;
    int Nc, colb;
    if (bx < 16)      { C = C0; Nc = 2048; colb = bx * 128; }
    else if (bx < 20) { C = C1; Nc = 512;  colb = (bx - 16) * 128; }
    else              { C = C2; Nc = 512;  colb = (bx - 20) * 128; }

#pragma unroll
    for (int mf = 0; mf < 2; mf++) {
#pragma unroll
        for (int nf = 0; nf < 8; nf++) {
            int row = by * 128 + warp_m * 32 + mf * 16 + g;
            int col = colb + warp_n * 64 + nf * 8 + 2 * tg;
            float* cp = C + (size_t)row * Nc + col;
            *(float2*)cp            = make_float2(acc[mf][nf][0], acc[mf][nf][1]);
            *(float2*)(cp + 8 * Nc) = make_float2(acc[mf][nf][2], acc[mf][nf][3]);
        }
    }
}

// ---------------------------------------------------------------------------
// BF16 tensor-core attention (unchanged from R12)
// ---------------------------------------------------------------------------
#define QT 32
#define CH 64
#define QST 72
#define VST 72
#define SSP 1028
#define NQT (SS/QT)     // 32
#define ATTN_SMEM (9216 + 18432 + QT*SSP*4)   // 159232

__global__ __launch_bounds__(512) void attn_kernel(float* __restrict__ aw)
{
    extern __shared__ char smc[];
    __nv_bfloat16* sQh = (__nv_bfloat16*)smc;
    __nv_bfloat16* sQl = sQh + QT * QST;
    __nv_bfloat16* sKh = sQl + QT * QST;
    __nv_bfloat16* sKl = sKh + 4608;
    float* sS = (float*)(sKl + 4608);

    const int qt = blockIdx.x & (NQT - 1);
    const int bh = blockIdx.x / NQT;
    const int b  = bh / NH;
    const int h  = bh % NH;
    const int kvh = h / (NH / NKV);
    const int tid = threadIdx.x;
    const int w = tid >> 5, lane = tid & 31;
    const int g = lane >> 2, tg = lane & 3;
    const int mq = (w >> 3) * 16;
    const int nc = w & 7;
    const int q0 = qt * QT;
    const float scaling = 0.125f;

    const int nch  = (q0 + QT + CH - 1) / CH;
    const int klim = nch * CH;

    // --- Q tile via cp.async (pre-split bf16) ---
    {
        int halfsel = tid >> 8;
        int idx = tid & 255;
        int r = idx >> 3, ch = idx & 7;
        const __nv_bfloat16* src = (halfsel ? g_Ql : g_Qh)
            + (size_t)(b * SS + q0 + r) * QW + h * HD + ch * 8;
        __nv_bfloat16* dst = (halfsel ? sQl : sQh) + r * QST + ch * 8;
        cp16((unsigned int)__cvta_generic_to_shared(dst), src);
        asm volatile("cp.async.commit_group;\n");
    }

    // --- QK^T over nch chunks ---
    for (int kt = 0; kt < nch; kt++) {
        __syncthreads();
#pragma unroll
        for (int i = 0; i < 2; i++) {
            int c = i * 512 + tid;
            int halfsel = c >> 9;
            int rem = c & 511;
            int kr = rem >> 3, ch = rem & 7;
            const __nv_bfloat16* src = (halfsel ? g_Kl : g_Kh)
                + (size_t)(b * SS + kt * CH + kr) * KW + kvh * HD + ch * 8;
            __nv_bfloat16* dst = (halfsel ? sKl : sKh) + kr * QST + ch * 8;
            cp16((unsigned int)__cvta_generic_to_shared(dst), src);
        }
        asm volatile("cp.async.commit_group;\n");
        asm volatile("cp.async.wait_group 0;\n");
        __syncthreads();

        float acc[4] = {0.f, 0.f, 0.f, 0.f};
#pragma unroll
        for (int kk = 0; kk < 4; kk++) {
            int abase = (mq + g) * QST + kk * 16 + 2 * tg;
            unsigned int ah[4], al[4];
            ah[0] = *(const unsigned int*)&sQh[abase];
            ah[1] = *(const unsigned int*)&sQh[abase + 8 * QST];
            ah[2] = *(const unsigned int*)&sQh[abase + 8];
            ah[3] = *(const unsigned int*)&sQh[abase + 8 * QST + 8];
            al[0] = *(const unsigned int*)&sQl[abase];
            al[1] = *(const unsigned int*)&sQl[abase + 8 * QST];
            al[2] = *(const unsigned int*)&sQl[abase + 8];
            al[3] = *(const unsigned int*)&sQl[abase + 8 * QST + 8];
            int bb = (nc * 8 + g) * QST + kk * 16 + 2 * tg;
            unsigned int bh2[2], bl2[2];
            bh2[0] = *(const unsigned int*)&sKh[bb];
            bh2[1] = *(const unsigned int*)&sKh[bb + 8];
            bl2[0] = *(const unsigned int*)&sKl[bb];
            bl2[1] = *(const unsigned int*)&sKl[bb + 8];
            mma_bf16(acc, ah, bl2);
            mma_bf16(acc, al, bh2);
            mma_bf16(acc, ah, bh2);
        }
        const int col = kt * CH + nc * 8 + 2 * tg;
        const int r0q = q0 + mq + g, r1q = q0 + mq + g + 8;
        float v00 = acc[0] * scaling + ((col     > r0q) ? -1e9f : 0.f);
        float v01 = acc[1] * scaling + ((col + 1 > r0q) ? -1e9f : 0.f);
        float v10 = acc[2] * scaling + ((col     > r1q) ? -1e9f : 0.f);
        float v11 = acc[3] * scaling + ((col + 1 > r1q) ? -1e9f : 0.f);
        *(float2*)(sS + (mq + g) * SSP + col)     = make_float2(v00, v01);
        *(float2*)(sS + (mq + g + 8) * SSP + col) = make_float2(v10, v11);
    }
    __syncthreads();

    // --- softmax ---
    {
        for (int rw = 0; rw < 2; rw++) {
            int r = w * 2 + rw;
            float* row = sS + r * SSP;
            float m = -INFINITY;
            for (int cc = lane; cc < klim; cc += 32) m = fmaxf(m, row[cc]);
#pragma unroll
            for (int o = 16; o; o >>= 1) m = fmaxf(m, __shfl_xor_sync(0xffffffffu, m, o));
            float ssum = 0.f;
            for (int cc = lane; cc < klim; cc += 32) {
                float p = __expf(row[cc] - m);
                row[cc] = p;
                ssum += p;
            }
#pragma unroll
            for (int o = 16; o; o >>= 1) ssum += __shfl_xor_sync(0xffffffffu, ssum, o);
            float inv = 1.f / ssum;
            float* awrow = aw + ((size_t)(bh * SS + q0 + r)) * SS;
            for (int cc = lane; cc < klim; cc += 32) {
                float p = row[cc] * inv;
                row[cc] = p;
                awrow[cc] = p;
            }
            for (int cc = klim + lane; cc < SS; cc += 32) awrow[cc] = 0.f;
        }
    }

    // --- PV over nch chunks (V^T in smem) ---
    float oacc[4] = {0.f, 0.f, 0.f, 0.f};
    for (int vt = 0; vt < nch; vt++) {
        __syncthreads();
        for (int i = tid; i < CH * 32; i += 512) {
            int key = i >> 5, d2 = i & 31;
            size_t go = (size_t)(b * SS + vt * CH + key) * KW + kvh * HD + d2 * 2;
            __nv_bfloat162 vh = *(const __nv_bfloat162*)(g_Vh + go);
            __nv_bfloat162 vl = *(const __nv_bfloat162*)(g_Vl + go);
            sKh[(2 * d2) * VST + key]     = vh.x;
            sKh[(2 * d2 + 1) * VST + key] = vh.y;
            sKl[(2 * d2) * VST + key]     = vl.x;
            sKl[(2 * d2 + 1) * VST + key] = vl.y;
        }
        __syncthreads();

#pragma unroll
        for (int kk = 0; kk < 4; kk++) {
            const int col0 = vt * CH + kk * 16 + 2 * tg;
            float2 q00 = *(const float2*)(sS + (mq + g) * SSP + col0);
            float2 q01 = *(const float2*)(sS + (mq + g) * SSP + col0 + 8);
            float2 q10 = *(const float2*)(sS + (mq + g + 8) * SSP + col0);
            float2 q11 = *(const float2*)(sS + (mq + g + 8) * SSP + col0 + 8);

            __nv_bfloat16 h00x = __float2bfloat16(q00.x), h00y = __float2bfloat16(q00.y);
            __nv_bfloat16 h01x = __float2bfloat16(q01.x), h01y = __float2bfloat16(q01.y);
            __nv_bfloat16 h10x = __float2bfloat16(q10.x), h10y = __float2bfloat16(q10.y);
            __nv_bfloat16 h11x = __float2bfloat16(q11.x), h11y = __float2bfloat16(q11.y);

            unsigned int ah[4], al[4];
            ah[0] = packbf(h00x, h00y);
            ah[1] = packbf(h10x, h10y);
            ah[2] = packbf(h01x, h01y);
            ah[3] = packbf(h11x, h11y);
            al[0] = packbf(__float2bfloat16(q00.x - __bfloat162float(h00x)),
                           __float2bfloat16(q00.y - __bfloat162float(h00y)));
            al[1] = packbf(__float2bfloat16(q10.x - __bfloat162float(h10x)),
                           __float2bfloat16(q10.y - __bfloat162float(h10y)));
            al[2] = packbf(__float2bfloat16(q01.x - __bfloat162float(h01x)),
                           __float2bfloat16(q01.y - __bfloat162float(h01y)));
            al[3] = packbf(__float2bfloat16(q11.x - __bfloat162float(h11x)),
                           __float2bfloat16(q11.y - __bfloat162float(h11y)));

            int bb = (nc * 8 + g) * VST + kk * 16 + 2 * tg;
            unsigned int bh2[2], bl2[2];
            bh2[0] = *(const unsigned int*)&sKh[bb];
            bh2[1] = *(const unsigned int*)&sKh[bb + 8];
            bl2[0] = *(const unsigned int*)&sKl[bb];
            bl2[1] = *(const unsigned int*)&sKl[bb + 8];
            mma_bf16(oacc, ah, bl2);
            mma_bf16(oacc, al, bh2);
            mma_bf16(oacc, ah, bh2);
        }
    }

    // write AO as bf16 hi/lo (feeds O-proj bf16 GEMM)
    {
        int r0 = b * SS + q0 + mq + g;
        int r1 = r0 + 8;
        int col = h * HD + nc * 8 + 2 * tg;
#pragma unroll
        for (int i = 0; i < 4; i++) {
            int rr = (i >> 1) ? r1 : r0;
            int cc = col + (i & 1);
            float v = oacc[i];
            __nv_bfloat16 hb = __float2bfloat16(v);
            g_AOh[(size_t)rr * QW + cc] = hb;
            g_AOl[(size_t)rr * QW + cc] = __float2bfloat16(v - __bfloat162float(hb));
        }
    }
}

// ---------------------------------------------------------------------------
// Launch
// ---------------------------------------------------------------------------
extern "C" void kernel_launch(void* const* d_in, const int* in_sizes, int n_in,
                              void* d_out, int out_size)
{
    const float* x    = (const float*)d_in[0];
    const float* cs   = (const float*)d_in[1];
    const float* sn   = (const float*)d_in[2];
    // d_in[3] = attention_mask (pure causal; reproduced analytically)
    const float* Wq   = (const float*)d_in[4];
    const float* Wk   = (const float*)d_in[5];
    const float* Wv   = (const float*)d_in[6];
    const float* Wo   = (const float*)d_in[7];

    float* out = (float*)d_out;
    float* aw  = out + (size_t)NROWS * HH;

    float *Qp, *Kp, *Vp;
    __nv_bfloat16 *xh, *xl, *Wallh, *Walll, *Woh, *Wol, *AOh, *AOl;
    __nv_bfloat16 *Qh, *Ql, *Kh, *Kl, *Vh, *Vl;
    cudaGetSymbolAddress((void**)&Qp,    g_Q);
    cudaGetSymbolAddress((void**)&Kp,    g_K);
    cudaGetSymbolAddress((void**)&Vp,    g_V);
    cudaGetSymbolAddress((void**)&xh,    g_xh);
    cudaGetSymbolAddress((void**)&xl,    g_xl);
    cudaGetSymbolAddress((void**)&Wallh, g_Wallh);
    cudaGetSymbolAddress((void**)&Walll, g_Walll);
    cudaGetSymbolAddress((void**)&Woh,   g_Woh);
    cudaGetSymbolAddress((void**)&Wol,   g_Wol);
    cudaGetSymbolAddress((void**)&AOh,   g_AOh);
    cudaGetSymbolAddress((void**)&AOl,   g_AOl);
    cudaGetSymbolAddress((void**)&Qh,    g_Qh);
    cudaGetSymbolAddress((void**)&Ql,    g_Ql);
    cudaGetSymbolAddress((void**)&Kh,    g_Kh);
    cudaGetSymbolAddress((void**)&Kl,    g_Kl);
    cudaGetSymbolAddress((void**)&Vh,    g_Vh);
    cudaGetSymbolAddress((void**)&Vl,    g_Vl);

    cudaFuncSetAttribute(attn_kernel, cudaFuncAttributeMaxDynamicSharedMemorySize, ATTN_SMEM);
    cudaFuncSetAttribute(gemm3, cudaFuncAttributeMaxDynamicSharedMemorySize, HGEMM_SMEM);

    // Split inputs to bf16 hi/lo (weights into combined [3072][2048] buffer)
    {
        int n = NROWS * HH;
        split_kernel<<<(n + 255) / 256, 256>>>(x, xh, xl, n);
        dim3 blk(32, 8);
        splitT_kernel<<<dim3(QW / 32, HH / 32), blk>>>(Wq, Wallh, Walll, HH, QW);
        splitT_kernel<<<dim3(KW / 32, HH / 32), blk>>>(
            Wk, Wallh + (size_t)QW * HH, Walll + (size_t)QW * HH, HH, KW);
        splitT_kernel<<<dim3(KW / 32, HH / 32), blk>>>(
            Wv, Wallh + (size_t)(QW + KW) * HH, Walll + (size_t)(QW + KW) * HH, HH, KW);
        splitT_kernel<<<dim3(HH / 32, QW / 32), blk>>>(Wo, Woh, Wol, QW, HH);
    }

    // Fused QKV projection (one launch)
    {
        dim3 g(NALL / 128, NROWS / 128);   // (24, 32)
        gemm3<<<g, 256, HGEMM_SMEM>>>(xh, xl, Wallh, Walll, Qp, Kp, Vp);
    }

    // RoPE + split Q/K; split V
    {
        int totq = NROWS * NH * 32;
        rope_split_kernel<<<(totq + 255) / 256, 256>>>(Qp, cs, sn, NH, Qh, Ql);
        int totk = NROWS * NKV * 32;
        rope_split_kernel<<<(totk + 255) / 256, 256>>>(Kp, cs, sn, NKV, Kh, Kl);
        int nv = NROWS * KW;
        split_kernel<<<(nv + 255) / 256, 256>>>(Vp, Vh, Vl, nv);
    }

    // Attention (+ aw output, AO bf16 split)
    {
        int grid = BB * NH * NQT;   // 4096
        attn_kernel<<<grid, 512, ATTN_SMEM>>>(aw);
    }

    // Output projection (same kernel, bx<16 path only)
    {
        dim3 g(QW / 128, NROWS / 128);     // (16, 32)
        gemm3<<<g, 256, HGEMM_SMEM>>>(AOh, AOl, Woh, Wol, out, nullptr, nullptr);
    }

    (void)in_sizes; (void)n_in; (void)out_size;
}